// round 7
// baseline (speedup 1.0000x reference)
#include <cuda_runtime.h>
#include <cuda_bf16.h>

// Problem constants
#define BATCH 4
#define CH    256
#define G     8
#define HD    32
#define L     3136      // 56*56
#define BG    32        // BATCH*G
#define TJ    64
#define TK    64
#define NT    49        // L/64
#define LOG2E 1.4426950408889634f

// Scratch (static device arrays; no allocations allowed)
__device__ float g_q[BG * HD * L];   // (bg, d, l), q pre-scaled by log2(e)
__device__ float g_k[BG * HD * L];   // (bg, d, l)
__device__ float g_v[BG * HD * L];   // (bg, d, l)
__device__ float g_m[BG * L];        // row max (log2 domain)
__device__ float g_rz[BG * L];       // 1 / row sum

// ---------------------------------------------------------------------------
// Kernel 1: grouped 1x1 conv -> q, k, v.  q scaled by log2(e).
// grid (49, 32), block 256
// ---------------------------------------------------------------------------
__global__ void qkv_kernel(const float* __restrict__ x,
                           const float* __restrict__ Wq, const float* __restrict__ bq,
                           const float* __restrict__ Wk, const float* __restrict__ bk,
                           const float* __restrict__ Wv, const float* __restrict__ bv)
{
    int bg = blockIdx.y;
    int l0 = blockIdx.x * 64;
    int b = bg >> 3, g = bg & 7;

    __shared__ float wqs[HD * HD], wks[HD * HD], wvs[HD * HD];
    __shared__ float bqs[HD], bks[HD], bvs[HD];
    __shared__ float xs[HD][64];

    int tid = threadIdx.x;
    for (int i = tid; i < HD * HD; i += 256) {
        wqs[i] = Wq[g * HD * HD + i] * LOG2E;
        wks[i] = Wk[g * HD * HD + i];
        wvs[i] = Wv[g * HD * HD + i];
    }
    if (tid < HD) {
        bqs[tid] = bq[g * HD + tid] * LOG2E;
        bks[tid] = bk[g * HD + tid];
        bvs[tid] = bv[g * HD + tid];
    }
    const float* xp = x + ((size_t)b * CH + g * HD) * L + l0;
    for (int i = tid; i < HD * 64; i += 256) {
        int d = i >> 6, l = i & 63;
        xs[d][l] = xp[(size_t)d * L + l];
    }
    __syncthreads();

    int l  = tid & 63;
    int o0 = (tid >> 6) * 8;
    float qa[8], ka[8], va[8];
#pragma unroll
    for (int r = 0; r < 8; r++) { qa[r] = bqs[o0 + r]; ka[r] = bks[o0 + r]; va[r] = bvs[o0 + r]; }
#pragma unroll
    for (int i = 0; i < HD; i++) {
        float xv = xs[i][l];
#pragma unroll
        for (int r = 0; r < 8; r++) {
            qa[r] += wqs[(o0 + r) * HD + i] * xv;
            ka[r] += wks[(o0 + r) * HD + i] * xv;
            va[r] += wvs[(o0 + r) * HD + i] * xv;
        }
    }
    size_t base = (size_t)bg * HD * L + l0 + l;
#pragma unroll
    for (int r = 0; r < 8; r++) {
        g_q[base + (size_t)(o0 + r) * L] = qa[r];
        g_k[base + (size_t)(o0 + r) * L] = ka[r];
        g_v[base + (size_t)(o0 + r) * L] = va[r];
    }
}

// ---------------------------------------------------------------------------
// Kernel 2: per-row online softmax stats over e[j,k] = q_j . k_k (log2 domain)
// grid (49, 32), block 256.  Thread (jg, kg) owns 4 rows x 4 cols per tile.
// ---------------------------------------------------------------------------
__global__ void pass1_kernel()
{
    int bg = blockIdx.y;
    int j0 = blockIdx.x * TJ;

    __shared__ float qs[HD][TJ];
    __shared__ float ks[HD][TK];

    int tid = threadIdx.x;
    const float* qp = g_q + (size_t)bg * HD * L;
    const float* kp = g_k + (size_t)bg * HD * L;

    for (int i = tid; i < HD * TJ; i += 256) {
        int d = i >> 6, jj = i & 63;
        qs[d][jj] = qp[(size_t)d * L + j0 + jj];
    }

    int jg = tid >> 4;   // 0..15 (row group); 16 lanes per row set = half warp
    int kg = tid & 15;   // 0..15 (col group)

    float m[4], s[4];
#pragma unroll
    for (int r = 0; r < 4; r++) { m[r] = -1e30f; s[r] = 0.f; }

    for (int kt = 0; kt < NT; kt++) {
        __syncthreads();
        for (int i = tid; i < HD * TK; i += 256) {
            int d = i >> 6, kk = i & 63;
            ks[d][kk] = kp[(size_t)d * L + kt * TK + kk];
        }
        __syncthreads();

        float e[4][4];
#pragma unroll
        for (int a = 0; a < 4; a++)
#pragma unroll
            for (int c = 0; c < 4; c++) e[a][c] = 0.f;

#pragma unroll
        for (int d = 0; d < HD; d++) {
            float4 qv = *(const float4*)&qs[d][jg * 4];
            float4 kv = *(const float4*)&ks[d][kg * 4];
            float qq[4] = {qv.x, qv.y, qv.z, qv.w};
            float kk2[4] = {kv.x, kv.y, kv.z, kv.w};
#pragma unroll
            for (int a = 0; a < 4; a++)
#pragma unroll
                for (int c = 0; c < 4; c++) e[a][c] += qq[a] * kk2[c];
        }

#pragma unroll
        for (int a = 0; a < 4; a++) {
            float mx = fmaxf(fmaxf(e[a][0], e[a][1]), fmaxf(e[a][2], e[a][3]));
            float mn = fmaxf(m[a], mx);
            float ss = exp2f(e[a][0] - mn) + exp2f(e[a][1] - mn)
                     + exp2f(e[a][2] - mn) + exp2f(e[a][3] - mn);
            s[a] = s[a] * exp2f(m[a] - mn) + ss;
            m[a] = mn;
        }
    }

    // reduce (m, s) across the 16 lanes sharing each row
#pragma unroll
    for (int mask = 8; mask; mask >>= 1) {
#pragma unroll
        for (int a = 0; a < 4; a++) {
            float om = __shfl_xor_sync(0xffffffff, m[a], mask);
            float os = __shfl_xor_sync(0xffffffff, s[a], mask);
            float mn = fmaxf(m[a], om);
            s[a] = s[a] * exp2f(m[a] - mn) + os * exp2f(om - mn);
            m[a] = mn;
        }
    }
    if (kg == 0) {
#pragma unroll
        for (int a = 0; a < 4; a++) {
            int j = j0 + jg * 4 + a;
            g_m[bg * L + j]  = m[a];
            g_rz[bg * L + j] = 1.0f / s[a];
        }
    }
}

// ---------------------------------------------------------------------------
// Kernel 3: out[d,k] = sum_j exp2(e[j,k]-m_j) * v[d,j]/Z_j   (+ x residual)
// grid (49, 32), block 256.  Block owns 64 output columns x all 32 d.
// ---------------------------------------------------------------------------
__global__ void pass2_kernel(const float* __restrict__ x, float* __restrict__ out)
{
    int bg = blockIdx.y;
    int k0 = blockIdx.x * TK;

    __shared__ float ks2[HD][TK];          // K for our columns (the "queries")
    __shared__ float qs[HD][TJ];           // Q tile (the "keys")
    __shared__ float wst[TJ][HD + 4];      // w = v/Z, transposed [jj][d]
    __shared__ float ps[TJ][TK + 4];       // P tile
    __shared__ float ms[TJ];

    int tid = threadIdx.x;
    const float* qp = g_q + (size_t)bg * HD * L;
    const float* kp = g_k + (size_t)bg * HD * L;
    const float* vp = g_v + (size_t)bg * HD * L;

    for (int i = tid; i < HD * TK; i += 256) {
        int d = i >> 6, kk = i & 63;
        ks2[d][kk] = kp[(size_t)d * L + k0 + kk];
    }

    int jg = tid >> 4, kg = tid & 15;   // P-compute mapping
    int kq = tid & 63;                  // out col
    int dg = tid >> 6;                  // 0..3 -> d base = dg*8

    float acc[8];
#pragma unroll
    for (int r = 0; r < 8; r++) acc[r] = 0.f;

    for (int jt = 0; jt < NT; jt++) {
        __syncthreads();
        int j0 = jt * TJ;
        for (int i = tid; i < HD * TJ; i += 256) {
            int d = i >> 6, jj = i & 63;
            qs[d][jj] = qp[(size_t)d * L + j0 + jj];
            float rz = g_rz[bg * L + j0 + jj];
            wst[jj][d] = vp[(size_t)d * L + j0 + jj] * rz;
        }
        if (tid < TJ) ms[tid] = g_m[bg * L + j0 + tid];
        __syncthreads();

        // P = exp2(Q^T Ks - m)
        float e[4][4];
#pragma unroll
        for (int a = 0; a < 4; a++)
#pragma unroll
            for (int c = 0; c < 4; c++) e[a][c] = 0.f;
#pragma unroll
        for (int d = 0; d < HD; d++) {
            float4 qv = *(const float4*)&qs[d][jg * 4];
            float4 kv = *(const float4*)&ks2[d][kg * 4];
            float qq[4] = {qv.x, qv.y, qv.z, qv.w};
            float kk2[4] = {kv.x, kv.y, kv.z, kv.w};
#pragma unroll
            for (int a = 0; a < 4; a++)
#pragma unroll
                for (int c = 0; c < 4; c++) e[a][c] += qq[a] * kk2[c];
        }
#pragma unroll
        for (int a = 0; a < 4; a++) {
            float mj = ms[jg * 4 + a];
            float4 pv;
            pv.x = exp2f(e[a][0] - mj);
            pv.y = exp2f(e[a][1] - mj);
            pv.z = exp2f(e[a][2] - mj);
            pv.w = exp2f(e[a][3] - mj);
            *(float4*)&ps[jg * 4 + a][kg * 4] = pv;
        }
        __syncthreads();

        // out[dg*8 + r][kq] += sum_jj P[jj][kq] * w[jj][dg*8 + r]
#pragma unroll 4
        for (int jj = 0; jj < TJ; jj++) {
            float p = ps[jj][kq];
            float4 w0 = *(const float4*)&wst[jj][dg * 8];
            float4 w1 = *(const float4*)&wst[jj][dg * 8 + 4];
            acc[0] += p * w0.x; acc[1] += p * w0.y;
            acc[2] += p * w0.z; acc[3] += p * w0.w;
            acc[4] += p * w1.x; acc[5] += p * w1.y;
            acc[6] += p * w1.z; acc[7] += p * w1.w;
        }
    }

    // epilogue: residual add, write NCHW
    int b = bg >> 3, g = bg & 7;
    size_t cbase = ((size_t)b * CH + g * HD + dg * 8) * L + k0 + kq;
#pragma unroll
    for (int r = 0; r < 8; r++) {
        out[cbase + (size_t)r * L] = acc[r] + x[cbase + (size_t)r * L];
    }
}

// ---------------------------------------------------------------------------
extern "C" void kernel_launch(void* const* d_in, const int* in_sizes, int n_in,
                              void* d_out, int out_size)
{
    (void)in_sizes; (void)n_in; (void)out_size;
    const float* x  = (const float*)d_in[0];
    const float* Wq = (const float*)d_in[1];
    const float* bq = (const float*)d_in[2];
    const float* Wk = (const float*)d_in[3];
    const float* bk = (const float*)d_in[4];
    const float* Wv = (const float*)d_in[5];
    const float* bv = (const float*)d_in[6];
    float* out = (float*)d_out;

    dim3 grid(NT, BG);
    qkv_kernel<<<grid, 256>>>(x, Wq, bq, Wk, bk, Wv, bv);
    pass1_kernel<<<grid, 256>>>();
    pass2_kernel<<<grid, 256>>>(x, out);
}

// round 8
// speedup vs baseline: 4.1904x; 4.1904x over previous
#include <cuda_runtime.h>
#include <cuda_bf16.h>

// Problem constants
#define BATCH 4
#define CH    256
#define G     8
#define HD    32
#define L     3136      // 56*56
#define BG    32        // BATCH*G
#define NT    49        // L/64
#define LOG2E 1.4426950408889634f

// Scratch (static device arrays; no allocations allowed)
__device__ float g_q[BG * L * HD];   // (bg, l, d)  TRANSPOSED, tf32-rounded, scaled by log2(e)
__device__ float g_k[BG * HD * L];   // (bg, d, l)  tf32-rounded
__device__ float g_v[BG * HD * L];   // (bg, d, l)  fp32
__device__ float g_rz[BG * L];       // 1 / row sum (no max needed: log2-domain logits bounded)

// ---------------------------------------------------------------------------
// helpers
// ---------------------------------------------------------------------------
__device__ __forceinline__ unsigned f2tf32(float f) {
    unsigned r;
    asm("cvt.rna.tf32.f32 %0, %1;" : "=r"(r) : "f"(f));
    return r;
}

__device__ __forceinline__ void mma_tf32(float c[4],
                                         unsigned a0, unsigned a1, unsigned a2, unsigned a3,
                                         unsigned b0, unsigned b1)
{
    asm volatile(
        "mma.sync.aligned.m16n8k8.row.col.f32.tf32.tf32.f32 "
        "{%0,%1,%2,%3}, {%4,%5,%6,%7}, {%8,%9}, {%0,%1,%2,%3};"
        : "+f"(c[0]), "+f"(c[1]), "+f"(c[2]), "+f"(c[3])
        : "r"(a0), "r"(a1), "r"(a2), "r"(a3), "r"(b0), "r"(b1));
}

// ---------------------------------------------------------------------------
// Kernel 1: grouped 1x1 conv -> q (transposed, scaled, tf32), k (tf32), v.
// grid (49, 32), block 256
// ---------------------------------------------------------------------------
__global__ void qkv_kernel(const float* __restrict__ x,
                           const float* __restrict__ Wq, const float* __restrict__ bq,
                           const float* __restrict__ Wk, const float* __restrict__ bk,
                           const float* __restrict__ Wv, const float* __restrict__ bv)
{
    int bg = blockIdx.y;
    int l0 = blockIdx.x * 64;
    int b = bg >> 3, g = bg & 7;

    __shared__ float wqs[HD * HD], wks[HD * HD], wvs[HD * HD];
    __shared__ float bqs[HD], bks[HD], bvs[HD];
    __shared__ float xs[HD][64];

    int tid = threadIdx.x;
    for (int i = tid; i < HD * HD; i += 256) {
        wqs[i] = Wq[g * HD * HD + i] * LOG2E;
        wks[i] = Wk[g * HD * HD + i];
        wvs[i] = Wv[g * HD * HD + i];
    }
    if (tid < HD) {
        bqs[tid] = bq[g * HD + tid] * LOG2E;
        bks[tid] = bk[g * HD + tid];
        bvs[tid] = bv[g * HD + tid];
    }
    const float* xp = x + ((size_t)b * CH + g * HD) * L + l0;
    for (int i = tid; i < HD * 64; i += 256) {
        int d = i >> 6, l = i & 63;
        xs[d][l] = xp[(size_t)d * L + l];
    }
    __syncthreads();

    int l  = tid & 63;
    int o0 = (tid >> 6) * 8;
    float qa[8], ka[8], va[8];
#pragma unroll
    for (int r = 0; r < 8; r++) { qa[r] = bqs[o0 + r]; ka[r] = bks[o0 + r]; va[r] = bvs[o0 + r]; }
#pragma unroll
    for (int i = 0; i < HD; i++) {
        float xv = xs[i][l];
#pragma unroll
        for (int r = 0; r < 8; r++) {
            qa[r] += wqs[(o0 + r) * HD + i] * xv;
            ka[r] += wks[(o0 + r) * HD + i] * xv;
            va[r] += wvs[(o0 + r) * HD + i] * xv;
        }
    }
    size_t basek = (size_t)bg * HD * L + l0 + l;
    size_t baseq = (size_t)bg * L * HD + (size_t)(l0 + l) * HD + o0;
#pragma unroll
    for (int r = 0; r < 8; r++) {
        g_q[baseq + r] = __uint_as_float(f2tf32(qa[r]));            // (l, d) layout
        g_k[basek + (size_t)(o0 + r) * L] = __uint_as_float(f2tf32(ka[r]));
        g_v[basek + (size_t)(o0 + r) * L] = va[r];
    }
}

// ---------------------------------------------------------------------------
// Kernel 2: row sums Z_j = sum_k exp2(e[j,k]),  e = Q^T K via tf32 mma.
// grid (49 j-tiles, 32 bg), block 256 (8 warps: wj=w>>1 row tile, wk=w&1 half)
// ---------------------------------------------------------------------------
__global__ void __launch_bounds__(256) pass1_kernel()
{
    int bg = blockIdx.y;
    int j0 = blockIdx.x * 64;

    __shared__ float qsT[64][36];   // [j][d], pad 36: fragment loads conflict-free
    __shared__ float ks [32][72];   // [d][k], pad 72: fragment loads conflict-free
    __shared__ float zsh[64];

    int tid = threadIdx.x;
    int w = tid >> 5, lane = tid & 31;
    int g = lane >> 2, t = lane & 3;

    const float* qp = g_q + (size_t)bg * L * HD;   // (l, d)
    const float* kp = g_k + (size_t)bg * HD * L;   // (d, l)

    for (int i = tid; i < 64 * 32; i += 256) {
        int jj = i >> 5, d = i & 31;
        qsT[jj][d] = qp[(size_t)(j0 + jj) * HD + d];
    }
    if (tid < 64) zsh[tid] = 0.f;

    int wj = w >> 1, wk = w & 1;
    int m0 = wj * 16;
    float s0 = 0.f, s1 = 0.f;

    for (int kt = 0; kt < NT; kt++) {
        __syncthreads();
        for (int i = tid; i < 32 * 64; i += 256) {
            int d = i >> 6, kk = i & 63;
            ks[d][kk] = kp[(size_t)d * L + kt * 64 + kk];
        }
        __syncthreads();

        float e[4][4];
#pragma unroll
        for (int nt = 0; nt < 4; nt++)
#pragma unroll
            for (int c = 0; c < 4; c++) e[nt][c] = 0.f;

#pragma unroll
        for (int ksl = 0; ksl < 4; ksl++) {
            int kd = ksl * 8;
            unsigned a0 = __float_as_uint(qsT[m0 + g    ][kd + t    ]);
            unsigned a1 = __float_as_uint(qsT[m0 + g + 8][kd + t    ]);
            unsigned a2 = __float_as_uint(qsT[m0 + g    ][kd + t + 4]);
            unsigned a3 = __float_as_uint(qsT[m0 + g + 8][kd + t + 4]);
#pragma unroll
            for (int nt = 0; nt < 4; nt++) {
                int n0 = wk * 32 + nt * 8;
                unsigned b0 = __float_as_uint(ks[kd + t    ][n0 + g]);
                unsigned b1 = __float_as_uint(ks[kd + t + 4][n0 + g]);
                mma_tf32(e[nt], a0, a1, a2, a3, b0, b1);
            }
        }
#pragma unroll
        for (int nt = 0; nt < 4; nt++) {
            s0 += exp2f(e[nt][0]) + exp2f(e[nt][1]);
            s1 += exp2f(e[nt][2]) + exp2f(e[nt][3]);
        }
    }

    // reduce across the 4 lanes sharing each row, then across wk halves
    s0 += __shfl_xor_sync(0xffffffffu, s0, 1);
    s0 += __shfl_xor_sync(0xffffffffu, s0, 2);
    s1 += __shfl_xor_sync(0xffffffffu, s1, 1);
    s1 += __shfl_xor_sync(0xffffffffu, s1, 2);
    if (t == 0) {
        atomicAdd(&zsh[m0 + g], s0);
        atomicAdd(&zsh[m0 + g + 8], s1);
    }
    __syncthreads();
    if (tid < 64) g_rz[bg * L + j0 + tid] = 1.0f / zsh[tid];
}

// ---------------------------------------------------------------------------
// Kernel 3: out[d,k] = sum_j exp2(e[j,k]) * v[d,j]/Z_j  (+ x residual)
// grid (49 k-tiles, 32 bg), block 256.
// QK mapping: warp w -> (wj=w>>1 j-rows, wk=w&1 k-half).
// PV mapping: warp w -> (mt=w>>2 d-half, n-tiles 2(w&3), 2(w&3)+1).
// ---------------------------------------------------------------------------
__global__ void __launch_bounds__(256) pass2_kernel(const float* __restrict__ x,
                                                    float* __restrict__ out)
{
    int bg = blockIdx.y;
    int k0 = blockIdx.x * 64;

    __shared__ float ks2[32][72];   // K tile   [d][k]
    __shared__ float qsT[64][36];   // Q tile   [j][d]
    __shared__ float ws [32][68];   // v/Z tile [d][j]
    __shared__ float ps [64][72];   // P tile   [j][k]

    int tid = threadIdx.x;
    int w = tid >> 5, lane = tid & 31;
    int g = lane >> 2, t = lane & 3;

    const float* qp  = g_q  + (size_t)bg * L * HD;
    const float* kp  = g_k  + (size_t)bg * HD * L;
    const float* vp  = g_v  + (size_t)bg * HD * L;
    const float* rzp = g_rz + bg * L;

    for (int i = tid; i < 32 * 64; i += 256) {
        int d = i >> 6, kk = i & 63;
        ks2[d][kk] = kp[(size_t)d * L + k0 + kk];
    }

    int wj = w >> 1, wk = w & 1, m0q = wj * 16;
    int mt = w >> 2, m0p = mt * 16, ntb = (w & 3) * 2;

    float acc[2][4];
#pragma unroll
    for (int q2 = 0; q2 < 2; q2++)
#pragma unroll
        for (int c = 0; c < 4; c++) acc[q2][c] = 0.f;

    for (int jt = 0; jt < NT; jt++) {
        int j0 = jt * 64;
        __syncthreads();   // prev PV done with ws/ps; prev QK done with qsT
        for (int i = tid; i < 64 * 32; i += 256) {
            int jj = i >> 5, d = i & 31;
            qsT[jj][d] = qp[(size_t)(j0 + jj) * HD + d];
        }
        for (int i = tid; i < 32 * 64; i += 256) {
            int d = i >> 6, jj = i & 63;
            float wv = vp[(size_t)d * L + j0 + jj] * rzp[j0 + jj];
            ws[d][jj] = __uint_as_float(f2tf32(wv));
        }
        __syncthreads();

        // ---- E = Q^T K (64j x 64k), tf32 mma ----
        float e[4][4];
#pragma unroll
        for (int nt = 0; nt < 4; nt++)
#pragma unroll
            for (int c = 0; c < 4; c++) e[nt][c] = 0.f;

#pragma unroll
        for (int ksl = 0; ksl < 4; ksl++) {
            int kd = ksl * 8;
            unsigned a0 = __float_as_uint(qsT[m0q + g    ][kd + t    ]);
            unsigned a1 = __float_as_uint(qsT[m0q + g + 8][kd + t    ]);
            unsigned a2 = __float_as_uint(qsT[m0q + g    ][kd + t + 4]);
            unsigned a3 = __float_as_uint(qsT[m0q + g + 8][kd + t + 4]);
#pragma unroll
            for (int nt = 0; nt < 4; nt++) {
                int n0 = wk * 32 + nt * 8;
                unsigned b0 = __float_as_uint(ks2[kd + t    ][n0 + g]);
                unsigned b1 = __float_as_uint(ks2[kd + t + 4][n0 + g]);
                mma_tf32(e[nt], a0, a1, a2, a3, b0, b1);
            }
        }

        // ---- P = exp2(E), round to tf32, store to smem ----
#pragma unroll
        for (int nt = 0; nt < 4; nt++) {
            int col = wk * 32 + nt * 8 + 2 * t;
            float2 p0, p1;
            p0.x = __uint_as_float(f2tf32(exp2f(e[nt][0])));
            p0.y = __uint_as_float(f2tf32(exp2f(e[nt][1])));
            p1.x = __uint_as_float(f2tf32(exp2f(e[nt][2])));
            p1.y = __uint_as_float(f2tf32(exp2f(e[nt][3])));
            *(float2*)&ps[m0q + g    ][col] = p0;
            *(float2*)&ps[m0q + g + 8][col] = p1;
        }
        __syncthreads();

        // ---- out += W * P  (M=32 d, N=64 k, K=64 j) ----
#pragma unroll
        for (int ksl = 0; ksl < 8; ksl++) {
            int kd = ksl * 8;
            unsigned a0 = __float_as_uint(ws[m0p + g    ][kd + t    ]);
            unsigned a1 = __float_as_uint(ws[m0p + g + 8][kd + t    ]);
            unsigned a2 = __float_as_uint(ws[m0p + g    ][kd + t + 4]);
            unsigned a3 = __float_as_uint(ws[m0p + g + 8][kd + t + 4]);
#pragma unroll
            for (int q2 = 0; q2 < 2; q2++) {
                int n0 = (ntb + q2) * 8;
                unsigned b0 = __float_as_uint(ps[kd + t    ][n0 + g]);
                unsigned b1 = __float_as_uint(ps[kd + t + 4][n0 + g]);
                mma_tf32(acc[q2], a0, a1, a2, a3, b0, b1);
            }
        }
    }

    // epilogue: residual add, write NCHW
    int b = bg >> 3, gh = bg & 7;
#pragma unroll
    for (int q2 = 0; q2 < 2; q2++) {
        int col = k0 + (ntb + q2) * 8 + 2 * t;
        size_t base0 = ((size_t)b * CH + gh * HD + m0p + g) * L + col;
        size_t base1 = base0 + (size_t)8 * L;
        out[base0    ] = acc[q2][0] + x[base0    ];
        out[base0 + 1] = acc[q2][1] + x[base0 + 1];
        out[base1    ] = acc[q2][2] + x[base1    ];
        out[base1 + 1] = acc[q2][3] + x[base1 + 1];
    }
}

// ---------------------------------------------------------------------------
extern "C" void kernel_launch(void* const* d_in, const int* in_sizes, int n_in,
                              void* d_out, int out_size)
{
    (void)in_sizes; (void)n_in; (void)out_size;
    const float* x  = (const float*)d_in[0];
    const float* Wq = (const float*)d_in[1];
    const float* bq = (const float*)d_in[2];
    const float* Wk = (const float*)d_in[3];
    const float* bk = (const float*)d_in[4];
    const float* Wv = (const float*)d_in[5];
    const float* bv = (const float*)d_in[6];
    float* out = (float*)d_out;

    dim3 grid(NT, BG);
    qkv_kernel<<<grid, 256>>>(x, Wq, bq, Wk, bk, Wv, bv);
    pass1_kernel<<<grid, 256>>>();
    pass2_kernel<<<grid, 256>>>(x, out);
}

// round 9
// speedup vs baseline: 4.4582x; 1.0639x over previous
#include <cuda_runtime.h>
#include <cuda_bf16.h>

// Problem constants
#define BATCH 4
#define CH    256
#define G     8
#define HD    32
#define L     3136      // 56*56
#define BG    32        // BATCH*G
#define NT    49        // 64-wide j tiles
#define NKT   25        // 128-wide k tiles (last covers only 64 cols)
#define LOG2E 1.4426950408889634f

// Scratch (static device arrays; no allocations allowed)
__device__ float g_q[BG * L * HD];   // (bg, l, d) transposed, tf32-rounded, scaled by log2(e)
__device__ float g_k[BG * HD * L];   // (bg, d, l) tf32-rounded
__device__ float g_v[BG * HD * L];   // (bg, d, l) fp32
__device__ float g_lz[BG * L];       // -log2(row sum)

// ---------------------------------------------------------------------------
// helpers
// ---------------------------------------------------------------------------
__device__ __forceinline__ unsigned f2tf32(float f) {
    unsigned r;
    asm("cvt.rna.tf32.f32 %0, %1;" : "=r"(r) : "f"(f));
    return r;
}

__device__ __forceinline__ void mma_tf32(float c[4],
                                         unsigned a0, unsigned a1, unsigned a2, unsigned a3,
                                         unsigned b0, unsigned b1)
{
    asm volatile(
        "mma.sync.aligned.m16n8k8.row.col.f32.tf32.tf32.f32 "
        "{%0,%1,%2,%3}, {%4,%5,%6,%7}, {%8,%9}, {%0,%1,%2,%3};"
        : "+f"(c[0]), "+f"(c[1]), "+f"(c[2]), "+f"(c[3])
        : "r"(a0), "r"(a1), "r"(a2), "r"(a3), "r"(b0), "r"(b1));
}

// ---------------------------------------------------------------------------
// Kernel 1: grouped 1x1 conv -> q (transposed, scaled, tf32), k (tf32), v.
// grid (49, 32), block 256
// ---------------------------------------------------------------------------
__global__ void qkv_kernel(const float* __restrict__ x,
                           const float* __restrict__ Wq, const float* __restrict__ bq,
                           const float* __restrict__ Wk, const float* __restrict__ bk,
                           const float* __restrict__ Wv, const float* __restrict__ bv)
{
    int bg = blockIdx.y;
    int l0 = blockIdx.x * 64;
    int b = bg >> 3, g = bg & 7;

    __shared__ float wqs[HD * HD], wks[HD * HD], wvs[HD * HD];
    __shared__ float bqs[HD], bks[HD], bvs[HD];
    __shared__ float xs[HD][64];

    int tid = threadIdx.x;
    for (int i = tid; i < HD * HD; i += 256) {
        wqs[i] = Wq[g * HD * HD + i] * LOG2E;
        wks[i] = Wk[g * HD * HD + i];
        wvs[i] = Wv[g * HD * HD + i];
    }
    if (tid < HD) {
        bqs[tid] = bq[g * HD + tid] * LOG2E;
        bks[tid] = bk[g * HD + tid];
        bvs[tid] = bv[g * HD + tid];
    }
    const float* xp = x + ((size_t)b * CH + g * HD) * L + l0;
    for (int i = tid; i < HD * 64; i += 256) {
        int d = i >> 6, l = i & 63;
        xs[d][l] = xp[(size_t)d * L + l];
    }
    __syncthreads();

    int l  = tid & 63;
    int o0 = (tid >> 6) * 8;
    float qa[8], ka[8], va[8];
#pragma unroll
    for (int r = 0; r < 8; r++) { qa[r] = bqs[o0 + r]; ka[r] = bks[o0 + r]; va[r] = bvs[o0 + r]; }
#pragma unroll
    for (int i = 0; i < HD; i++) {
        float xv = xs[i][l];
#pragma unroll
        for (int r = 0; r < 8; r++) {
            qa[r] += wqs[(o0 + r) * HD + i] * xv;
            ka[r] += wks[(o0 + r) * HD + i] * xv;
            va[r] += wvs[(o0 + r) * HD + i] * xv;
        }
    }
    size_t basek = (size_t)bg * HD * L + l0 + l;
    size_t baseq = (size_t)bg * L * HD + (size_t)(l0 + l) * HD + o0;
#pragma unroll
    for (int r = 0; r < 8; r++) {
        g_q[baseq + r] = __uint_as_float(f2tf32(qa[r]));
        g_k[basek + (size_t)(o0 + r) * L] = __uint_as_float(f2tf32(ka[r]));
        g_v[basek + (size_t)(o0 + r) * L] = va[r];
    }
}

// ---------------------------------------------------------------------------
// Kernel 2: Z_j = sum_k exp2(e[j,k]); stores -log2(Z).
// grid (49 j-tiles, 32 bg), block 256. Block tile 64j x 128k.
// Warp (wj = w>>2, wk = w&3) owns 32j x 32k.
// ---------------------------------------------------------------------------
__global__ void __launch_bounds__(256) pass1_kernel()
{
    int bg = blockIdx.y;
    int j0 = blockIdx.x * 64;

    __shared__ float qsT[64][36];    // [j][d]  (4g+t bank map: conflict-free)
    __shared__ float ks [32][136];   // [d][k]  (8t+g bank map: conflict-free)
    __shared__ float zsh[64];

    int tid = threadIdx.x;
    int w = tid >> 5, lane = tid & 31;
    int g = lane >> 2, t = lane & 3;
    int wj = w >> 2, wk = w & 3;
    int m0 = wj * 32, nb = wk * 32;

    const float* qp = g_q + (size_t)bg * L * HD;
    const float* kp = g_k + (size_t)bg * HD * L;

    for (int i = tid; i < 64 * 32; i += 256) {
        int jj = i >> 5, d = i & 31;
        qsT[jj][d] = qp[(size_t)(j0 + jj) * HD + d];
    }
    if (tid < 64) zsh[tid] = 0.f;

    float s[2][2] = {{0.f, 0.f}, {0.f, 0.f}};

    for (int kt = 0; kt < NKT; kt++) {
        __syncthreads();
        int kbase = kt * 128;
        for (int i = tid; i < 32 * 128; i += 256) {
            int d = i >> 7, kk = i & 127;
            int col = kbase + kk;
            ks[d][kk] = (col < L) ? kp[(size_t)d * L + col] : 0.f;
        }
        __syncthreads();

        float e[2][4][4];
#pragma unroll
        for (int mt = 0; mt < 2; mt++)
#pragma unroll
            for (int nt = 0; nt < 4; nt++)
#pragma unroll
                for (int c = 0; c < 4; c++) e[mt][nt][c] = 0.f;

#pragma unroll
        for (int ksl = 0; ksl < 4; ksl++) {
            int kd = ksl * 8;
            unsigned a[2][4];
#pragma unroll
            for (int mt = 0; mt < 2; mt++) {
                int r = m0 + mt * 16 + g;
                a[mt][0] = __float_as_uint(qsT[r    ][kd + t    ]);
                a[mt][1] = __float_as_uint(qsT[r + 8][kd + t    ]);
                a[mt][2] = __float_as_uint(qsT[r    ][kd + t + 4]);
                a[mt][3] = __float_as_uint(qsT[r + 8][kd + t + 4]);
            }
#pragma unroll
            for (int nt = 0; nt < 4; nt++) {
                unsigned b0 = __float_as_uint(ks[kd + t    ][nb + nt * 8 + g]);
                unsigned b1 = __float_as_uint(ks[kd + t + 4][nb + nt * 8 + g]);
                mma_tf32(e[0][nt], a[0][0], a[0][1], a[0][2], a[0][3], b0, b1);
                mma_tf32(e[1][nt], a[1][0], a[1][1], a[1][2], a[1][3], b0, b1);
            }
        }

        // tail tile: cols >= L are zero-filled (e=0); warps wk>=2 are fully OOB
        if (kt < NKT - 1 || wk < 2) {
#pragma unroll
            for (int mt = 0; mt < 2; mt++)
#pragma unroll
                for (int nt = 0; nt < 4; nt++) {
                    s[mt][0] += exp2f(e[mt][nt][0]) + exp2f(e[mt][nt][1]);
                    s[mt][1] += exp2f(e[mt][nt][2]) + exp2f(e[mt][nt][3]);
                }
        }
    }

    // reduce the 4 t-lanes of each row, then across the 4 k-warps via smem atomics
#pragma unroll
    for (int mask = 1; mask <= 2; mask <<= 1)
#pragma unroll
        for (int mt = 0; mt < 2; mt++)
#pragma unroll
            for (int r = 0; r < 2; r++)
                s[mt][r] += __shfl_xor_sync(0xffffffffu, s[mt][r], mask);
    if (t == 0) {
        atomicAdd(&zsh[m0 + g     ], s[0][0]);
        atomicAdd(&zsh[m0 + g + 8 ], s[0][1]);
        atomicAdd(&zsh[m0 + g + 16], s[1][0]);
        atomicAdd(&zsh[m0 + g + 24], s[1][1]);
    }
    __syncthreads();
    if (tid < 64) g_lz[bg * L + j0 + tid] = -log2f(zsh[tid]);
}

// ---------------------------------------------------------------------------
// Kernel 3: out[d,k] = sum_j exp2(e[j,k] + lz_j) * v[d,j]  (+ x residual)
// grid (25 k-tiles, 32 bg), block 256, dynamic smem.
// QK: warp (wj=w>>2, wk=w&3) -> 32j x 32k of the 64x128 E tile.
// PV: split-K over j halves: kh=w>>2, wm=(w>>1)&1, wn=w&1; warp 16d x 64k x 32j.
// ---------------------------------------------------------------------------
__global__ void __launch_bounds__(256) pass2_kernel(const float* __restrict__ x,
                                                    float* __restrict__ out)
{
    extern __shared__ float sm[];
    float (*ks2)[136] = (float(*)[136])sm;                               // 32 x 136
    float (*qsT)[36]  = (float(*)[36])(sm + 32 * 136);                   // 64 x 36
    float (*ws)[68]   = (float(*)[68])(sm + 32 * 136 + 64 * 36);         // 32 x 68
    float (*ps)[136]  = (float(*)[136])(sm + 32 * 136 + 64 * 36 + 32 * 68); // 64 x 136
    float* lzsh       = sm + 32 * 136 + 64 * 36 + 32 * 68 + 64 * 136;    // 64

    int bg = blockIdx.y;
    int k0 = blockIdx.x * 128;
    int tid = threadIdx.x;
    int w = tid >> 5, lane = tid & 31;
    int g = lane >> 2, t = lane & 3;
    int wj = w >> 2, wk = w & 3;
    int m0q = wj * 32, nbq = wk * 32;
    int kh = w >> 2, wm = (w >> 1) & 1, wn = w & 1;
    int m0p = wm * 16, nbp = wn * 64, kjb = kh * 32;

    const float* qp  = g_q  + (size_t)bg * L * HD;
    const float* kp  = g_k  + (size_t)bg * HD * L;
    const float* vp  = g_v  + (size_t)bg * HD * L;
    const float* lzp = g_lz + bg * L;

    for (int i = tid; i < 32 * 128; i += 256) {
        int d = i >> 7, kk = i & 127;
        int col = k0 + kk;
        ks2[d][kk] = (col < L) ? kp[(size_t)d * L + col] : 0.f;
    }

    float acc[8][4];
#pragma unroll
    for (int nt = 0; nt < 8; nt++)
#pragma unroll
        for (int c = 0; c < 4; c++) acc[nt][c] = 0.f;

    for (int jt = 0; jt < NT; jt++) {
        int j0 = jt * 64;
        __syncthreads();   // prev iter done with qsT/ws/ps
        for (int i = tid; i < 64 * 32; i += 256) {
            int jj = i >> 5, d = i & 31;
            qsT[jj][d] = qp[(size_t)(j0 + jj) * HD + d];
        }
        for (int i = tid; i < 32 * 64; i += 256) {
            int d = i >> 6, jj = i & 63;
            ws[d][jj] = vp[(size_t)d * L + j0 + jj];
        }
        if (tid < 64) lzsh[tid] = lzp[j0 + tid];
        __syncthreads();

        // ---- E = Q^T K (64j x 128k) ----
        float e[2][4][4];
#pragma unroll
        for (int mt = 0; mt < 2; mt++)
#pragma unroll
            for (int nt = 0; nt < 4; nt++)
#pragma unroll
                for (int c = 0; c < 4; c++) e[mt][nt][c] = 0.f;

#pragma unroll
        for (int ksl = 0; ksl < 4; ksl++) {
            int kd = ksl * 8;
            unsigned a[2][4];
#pragma unroll
            for (int mt = 0; mt < 2; mt++) {
                int r = m0q + mt * 16 + g;
                a[mt][0] = __float_as_uint(qsT[r    ][kd + t    ]);
                a[mt][1] = __float_as_uint(qsT[r + 8][kd + t    ]);
                a[mt][2] = __float_as_uint(qsT[r    ][kd + t + 4]);
                a[mt][3] = __float_as_uint(qsT[r + 8][kd + t + 4]);
            }
#pragma unroll
            for (int nt = 0; nt < 4; nt++) {
                unsigned b0 = __float_as_uint(ks2[kd + t    ][nbq + nt * 8 + g]);
                unsigned b1 = __float_as_uint(ks2[kd + t + 4][nbq + nt * 8 + g]);
                mma_tf32(e[0][nt], a[0][0], a[0][1], a[0][2], a[0][3], b0, b1);
                mma_tf32(e[1][nt], a[1][0], a[1][1], a[1][2], a[1][3], b0, b1);
            }
        }

        // ---- P = exp2(E + lz_j) -> ps ----
#pragma unroll
        for (int mt = 0; mt < 2; mt++) {
            int r = m0q + mt * 16 + g;
            float lz0 = lzsh[r], lz1 = lzsh[r + 8];
#pragma unroll
            for (int nt = 0; nt < 4; nt++) {
                int col = nbq + nt * 8 + 2 * t;
                *(float2*)&ps[r    ][col] = make_float2(exp2f(e[mt][nt][0] + lz0),
                                                        exp2f(e[mt][nt][1] + lz0));
                *(float2*)&ps[r + 8][col] = make_float2(exp2f(e[mt][nt][2] + lz1),
                                                        exp2f(e[mt][nt][3] + lz1));
            }
        }
        __syncthreads();

        // ---- acc += V * P  (M=32 d, N=128 k, K=64 j split across kh) ----
#pragma unroll
        for (int ksl = 0; ksl < 4; ksl++) {
            int kd = kjb + ksl * 8;
            unsigned a0 = __float_as_uint(ws[m0p + g    ][kd + t    ]);
            unsigned a1 = __float_as_uint(ws[m0p + g + 8][kd + t    ]);
            unsigned a2 = __float_as_uint(ws[m0p + g    ][kd + t + 4]);
            unsigned a3 = __float_as_uint(ws[m0p + g + 8][kd + t + 4]);
#pragma unroll
            for (int nt = 0; nt < 8; nt++) {
                unsigned b0 = __float_as_uint(ps[kd + t    ][nbp + nt * 8 + g]);
                unsigned b1 = __float_as_uint(ps[kd + t + 4][nbp + nt * 8 + g]);
                mma_tf32(acc[nt], a0, a1, a2, a3, b0, b1);
            }
        }
    }

    // ---- split-K reduction across kh pairs (reuse ps), then epilogue ----
    __syncthreads();
    if (kh == 1) {
#pragma unroll
        for (int nt = 0; nt < 8; nt++) {
            int col = nbp + nt * 8 + 2 * t;
            *(float2*)&ps[m0p + g    ][col] = make_float2(acc[nt][0], acc[nt][1]);
            *(float2*)&ps[m0p + g + 8][col] = make_float2(acc[nt][2], acc[nt][3]);
        }
    }
    __syncthreads();
    if (kh == 0) {
        int b = bg >> 3, gh = bg & 7;
#pragma unroll
        for (int nt = 0; nt < 8; nt++) {
            int col = nbp + nt * 8 + 2 * t;
            float2 r0 = *(float2*)&ps[m0p + g    ][col];
            float2 r1 = *(float2*)&ps[m0p + g + 8][col];
            int gcol = k0 + col;
            if (gcol < L) {
                size_t b0 = ((size_t)b * CH + gh * HD + m0p + g) * L + gcol;
                size_t b1 = b0 + (size_t)8 * L;
                out[b0    ] = acc[nt][0] + r0.x + x[b0    ];
                out[b0 + 1] = acc[nt][1] + r0.y + x[b0 + 1];
                out[b1    ] = acc[nt][2] + r1.x + x[b1    ];
                out[b1 + 1] = acc[nt][3] + r1.y + x[b1 + 1];
            }
        }
    }
}

// ---------------------------------------------------------------------------
extern "C" void kernel_launch(void* const* d_in, const int* in_sizes, int n_in,
                              void* d_out, int out_size)
{
    (void)in_sizes; (void)n_in; (void)out_size;
    const float* x  = (const float*)d_in[0];
    const float* Wq = (const float*)d_in[1];
    const float* bq = (const float*)d_in[2];
    const float* Wk = (const float*)d_in[3];
    const float* bk = (const float*)d_in[4];
    const float* Wv = (const float*)d_in[5];
    const float* bv = (const float*)d_in[6];
    float* out = (float*)d_out;

    const int SMEM2 = (32 * 136 + 64 * 36 + 32 * 68 + 64 * 136 + 64) * 4;
    cudaFuncSetAttribute(pass2_kernel, cudaFuncAttributeMaxDynamicSharedMemorySize, SMEM2);

    qkv_kernel<<<dim3(NT, BG), 256>>>(x, Wq, bq, Wk, bk, Wv, bv);
    pass1_kernel<<<dim3(NT, BG), 256>>>();
    pass2_kernel<<<dim3(NKT, BG), 256, SMEM2>>>(x, out);
}

// round 10
// speedup vs baseline: 6.4155x; 1.4390x over previous
#include <cuda_runtime.h>
#include <cuda_bf16.h>

// Problem constants
#define BATCH 4
#define CH    256
#define G     8
#define HD    32
#define L     3136      // 56*56
#define BG    32        // BATCH*G
#define NT    49        // 64-wide j tiles
#define NKT   25        // 128-wide k tiles (last covers only 64 cols)
#define LOG2E 1.4426950408889634f

// Scratch (static device arrays; no allocations allowed). 16B-aligned for cp.async.
__device__ __align__(256) float g_q[BG * L * HD];   // (bg, l, d) transposed, tf32, *log2(e)
__device__ __align__(256) float g_k[BG * HD * L];   // (bg, d, l) tf32-rounded
__device__ __align__(256) float g_v[BG * HD * L];   // (bg, d, l) fp32
__device__ __align__(256) float g_lz[BG * L];       // -log2(row sum)

// ---------------------------------------------------------------------------
// helpers
// ---------------------------------------------------------------------------
__device__ __forceinline__ unsigned f2tf32(float f) {
    unsigned r;
    asm("cvt.rna.tf32.f32 %0, %1;" : "=r"(r) : "f"(f));
    return r;
}

__device__ __forceinline__ float ex2(float x) {
    float r;
    asm("ex2.approx.ftz.f32 %0, %1;" : "=f"(r) : "f"(x));
    return r;
}

__device__ __forceinline__ void cp16(void* smem_dst, const void* gsrc) {
    unsigned s = (unsigned)__cvta_generic_to_shared(smem_dst);
    asm volatile("cp.async.cg.shared.global [%0], [%1], 16;" :: "r"(s), "l"(gsrc));
}
#define CP_COMMIT() asm volatile("cp.async.commit_group;")
#define CP_WAIT0()  asm volatile("cp.async.wait_group 0;")

__device__ __forceinline__ void mma_tf32(float c[4],
                                         unsigned a0, unsigned a1, unsigned a2, unsigned a3,
                                         unsigned b0, unsigned b1)
{
    asm volatile(
        "mma.sync.aligned.m16n8k8.row.col.f32.tf32.tf32.f32 "
        "{%0,%1,%2,%3}, {%4,%5,%6,%7}, {%8,%9}, {%0,%1,%2,%3};"
        : "+f"(c[0]), "+f"(c[1]), "+f"(c[2]), "+f"(c[3])
        : "r"(a0), "r"(a1), "r"(a2), "r"(a3), "r"(b0), "r"(b1));
}

// ---------------------------------------------------------------------------
// Kernel 1: grouped 1x1 conv -> q (transposed, scaled, tf32), k (tf32), v.
// grid (49, 32), block 256
// ---------------------------------------------------------------------------
__global__ void __launch_bounds__(256, 3)
qkv_kernel(const float* __restrict__ x,
           const float* __restrict__ Wq, const float* __restrict__ bq,
           const float* __restrict__ Wk, const float* __restrict__ bk,
           const float* __restrict__ Wv, const float* __restrict__ bv)
{
    int bg = blockIdx.y;
    int l0 = blockIdx.x * 64;
    int b = bg >> 3, g = bg & 7;

    __shared__ float wqs[HD * HD], wks[HD * HD], wvs[HD * HD];
    __shared__ float bqs[HD], bks[HD], bvs[HD];
    __shared__ float xs[HD][64];

    int tid = threadIdx.x;
    for (int i = tid; i < HD * HD; i += 256) {
        wqs[i] = Wq[g * HD * HD + i] * LOG2E;
        wks[i] = Wk[g * HD * HD + i];
        wvs[i] = Wv[g * HD * HD + i];
    }
    if (tid < HD) {
        bqs[tid] = bq[g * HD + tid] * LOG2E;
        bks[tid] = bk[g * HD + tid];
        bvs[tid] = bv[g * HD + tid];
    }
    const float* xp = x + ((size_t)b * CH + g * HD) * L + l0;
    for (int i = tid; i < HD * 64; i += 256) {
        int d = i >> 6, l = i & 63;
        xs[d][l] = xp[(size_t)d * L + l];
    }
    __syncthreads();

    int l  = tid & 63;
    int o0 = (tid >> 6) * 8;
    float qa[8], ka[8], va[8];
#pragma unroll
    for (int r = 0; r < 8; r++) { qa[r] = bqs[o0 + r]; ka[r] = bks[o0 + r]; va[r] = bvs[o0 + r]; }
#pragma unroll
    for (int i = 0; i < HD; i++) {
        float xv = xs[i][l];
#pragma unroll
        for (int r = 0; r < 8; r++) {
            qa[r] += wqs[(o0 + r) * HD + i] * xv;
            ka[r] += wks[(o0 + r) * HD + i] * xv;
            va[r] += wvs[(o0 + r) * HD + i] * xv;
        }
    }
    size_t basek = (size_t)bg * HD * L + l0 + l;
    size_t baseq = (size_t)bg * L * HD + (size_t)(l0 + l) * HD + o0;
#pragma unroll
    for (int r = 0; r < 8; r++) {
        g_q[baseq + r] = __uint_as_float(f2tf32(qa[r]));
        g_k[basek + (size_t)(o0 + r) * L] = __uint_as_float(f2tf32(ka[r]));
        g_v[basek + (size_t)(o0 + r) * L] = va[r];
    }
}

// ---------------------------------------------------------------------------
// Kernel 2: Z_j = sum_k exp2(e[j,k]); stores -log2(Z).
// grid (49 j-tiles, 32 bg), block 256. Block tile 64j x 128k.
// Double-buffered K tiles via cp.async; 1 barrier per iter.
// ---------------------------------------------------------------------------
__global__ void __launch_bounds__(256) pass1_kernel()
{
    int bg = blockIdx.y;
    int j0 = blockIdx.x * 64;

    __shared__ float qsT[64][36];       // [j][d]
    __shared__ float ks[2][32][136];    // [buf][d][k]
    __shared__ float zsh[64];

    int tid = threadIdx.x;
    int w = tid >> 5, lane = tid & 31;
    int g = lane >> 2, t = lane & 3;
    int wj = w >> 2, wk = w & 3;
    int m0 = wj * 32, nb = wk * 32;

    const float* qp = g_q + (size_t)bg * L * HD;
    const float* kp = g_k + (size_t)bg * HD * L;

    // issue first K tile (kt=0) into buf 0
    {
#pragma unroll
        for (int r = 0; r < 4; r++) {
            int task = tid + 256 * r;           // 1024 chunks: 32 rows x 32 x16B
            int row = task >> 5, ch = task & 31;
            cp16(&ks[0][row][ch * 4], kp + (size_t)row * L + ch * 4);
        }
        CP_COMMIT();
    }

    for (int i = tid; i < 64 * 32; i += 256) {
        int jj = i >> 5, d = i & 31;
        qsT[jj][d] = qp[(size_t)(j0 + jj) * HD + d];
    }
    if (tid < 64) zsh[tid] = 0.f;

    float s[2][2] = {{0.f, 0.f}, {0.f, 0.f}};
    int buf = 0;

    for (int kt = 0; kt < NKT; kt++) {
        CP_WAIT0();
        __syncthreads();     // ks[buf] ready; qsT/zsh ready on first iter

        if (kt + 1 < NKT) {
            int kbase = (kt + 1) * 128;
#pragma unroll
            for (int r = 0; r < 4; r++) {
                int task = tid + 256 * r;
                int row = task >> 5, ch = task & 31;
                int col = kbase + ch * 4;
                if (col < L)   // tail: cols >= L left stale; excluded below
                    cp16(&ks[buf ^ 1][row][ch * 4], kp + (size_t)row * L + col);
            }
            CP_COMMIT();
        }

        float e[2][4][4];
#pragma unroll
        for (int mt = 0; mt < 2; mt++)
#pragma unroll
            for (int nt = 0; nt < 4; nt++)
#pragma unroll
                for (int c = 0; c < 4; c++) e[mt][nt][c] = 0.f;

#pragma unroll
        for (int ksl = 0; ksl < 4; ksl++) {
            int kd = ksl * 8;
            unsigned a[2][4];
#pragma unroll
            for (int mt = 0; mt < 2; mt++) {
                int r = m0 + mt * 16 + g;
                a[mt][0] = __float_as_uint(qsT[r    ][kd + t    ]);
                a[mt][1] = __float_as_uint(qsT[r + 8][kd + t    ]);
                a[mt][2] = __float_as_uint(qsT[r    ][kd + t + 4]);
                a[mt][3] = __float_as_uint(qsT[r + 8][kd + t + 4]);
            }
#pragma unroll
            for (int nt = 0; nt < 4; nt++) {
                unsigned b0 = __float_as_uint(ks[buf][kd + t    ][nb + nt * 8 + g]);
                unsigned b1 = __float_as_uint(ks[buf][kd + t + 4][nb + nt * 8 + g]);
                mma_tf32(e[0][nt], a[0][0], a[0][1], a[0][2], a[0][3], b0, b1);
                mma_tf32(e[1][nt], a[1][0], a[1][1], a[1][2], a[1][3], b0, b1);
            }
        }

        // tail tile: warps wk>=2 are fully past L -> skip (stale smem harmless)
        if (kt < NKT - 1 || wk < 2) {
#pragma unroll
            for (int mt = 0; mt < 2; mt++)
#pragma unroll
                for (int nt = 0; nt < 4; nt++) {
                    s[mt][0] += ex2(e[mt][nt][0]) + ex2(e[mt][nt][1]);
                    s[mt][1] += ex2(e[mt][nt][2]) + ex2(e[mt][nt][3]);
                }
        }
        buf ^= 1;
    }

#pragma unroll
    for (int mask = 1; mask <= 2; mask <<= 1)
#pragma unroll
        for (int mt = 0; mt < 2; mt++)
#pragma unroll
            for (int r = 0; r < 2; r++)
                s[mt][r] += __shfl_xor_sync(0xffffffffu, s[mt][r], mask);
    if (t == 0) {
        atomicAdd(&zsh[m0 + g     ], s[0][0]);
        atomicAdd(&zsh[m0 + g + 8 ], s[0][1]);
        atomicAdd(&zsh[m0 + g + 16], s[1][0]);
        atomicAdd(&zsh[m0 + g + 24], s[1][1]);
    }
    __syncthreads();
    if (tid < 64) g_lz[bg * L + j0 + tid] = -log2f(zsh[tid]);
}

// ---------------------------------------------------------------------------
// Kernel 3: out[d,k] = sum_j exp2(e[j,k] + lz_j) * v[d,j]  (+ x residual)
// grid (25 k-tiles, 32 bg), block 256, dynamic smem (~88.5 KB).
// Double-buffered Q/V/lz tiles via cp.async; 2 barriers per iter.
// ---------------------------------------------------------------------------
__global__ void __launch_bounds__(256) pass2_kernel(const float* __restrict__ x,
                                                    float* __restrict__ out)
{
    extern __shared__ float sm[];
    float (*ks2)[136] = (float(*)[136])sm;                         // 32 x 136
    float (*qsT)[36]  = (float(*)[36])(sm + 32 * 136);             // 2 x 64 x 36
    float (*ws)[68]   = (float(*)[68])(sm + 32 * 136 + 2 * 64 * 36);   // 2 x 32 x 68
    float (*ps)[136]  = (float(*)[136])(sm + 32 * 136 + 2 * 64 * 36 + 2 * 32 * 68); // 64 x 136
    float* lzsh       = sm + 32 * 136 + 2 * 64 * 36 + 2 * 32 * 68 + 64 * 136;       // 2 x 64

    int bg = blockIdx.y;
    int k0 = blockIdx.x * 128;
    int tid = threadIdx.x;
    int w = tid >> 5, lane = tid & 31;
    int g = lane >> 2, t = lane & 3;
    int wj = w >> 2, wk = w & 3;
    int m0q = wj * 32, nbq = wk * 32;
    int kh = w >> 2, wm = (w >> 1) & 1, wn = w & 1;
    int m0p = wm * 16, nbp = wn * 64, kjb = kh * 32;

    const float* qp  = g_q  + (size_t)bg * L * HD;
    const float* kp  = g_k  + (size_t)bg * HD * L;
    const float* vp  = g_v  + (size_t)bg * HD * L;
    const float* lzp = g_lz + bg * L;

    // issue first j-tile (jt=0) loads into buf 0
    {
#pragma unroll
        for (int r = 0; r < 2; r++) {      // qsT: 512 chunks (64 rows x 8)
            int task = tid + 256 * r;
            int row = task >> 3, ch = task & 7;
            cp16(&qsT[row][ch * 4], qp + (size_t)row * HD + ch * 4);
        }
#pragma unroll
        for (int r = 0; r < 2; r++) {      // ws: 512 chunks (32 rows x 16)
            int task = tid + 256 * r;
            int row = task >> 4, ch = task & 15;
            cp16(&ws[row][ch * 4], vp + (size_t)row * L + ch * 4);
        }
        if (tid < 16) cp16(&lzsh[tid * 4], lzp + tid * 4);
        CP_COMMIT();
    }

    // K tile for our 128 columns (zero-filled past L), loaded once
    for (int i = tid; i < 32 * 128; i += 256) {
        int d = i >> 7, kk = i & 127;
        int col = k0 + kk;
        ks2[d][kk] = (col < L) ? kp[(size_t)d * L + col] : 0.f;
    }

    float acc[8][4];
#pragma unroll
    for (int nt = 0; nt < 8; nt++)
#pragma unroll
        for (int c = 0; c < 4; c++) acc[nt][c] = 0.f;

    int buf = 0;
    for (int jt = 0; jt < NT; jt++) {
        CP_WAIT0();
        __syncthreads();   // buf tiles ready; PV of prev iter done with ps

        if (jt + 1 < NT) {
            int jn = (jt + 1) * 64;
            int ob = buf ^ 1;
#pragma unroll
            for (int r = 0; r < 2; r++) {
                int task = tid + 256 * r;
                int row = task >> 3, ch = task & 7;
                cp16(&qsT[ob * 64 + row][ch * 4], qp + (size_t)(jn + row) * HD + ch * 4);
            }
#pragma unroll
            for (int r = 0; r < 2; r++) {
                int task = tid + 256 * r;
                int row = task >> 4, ch = task & 15;
                cp16(&ws[ob * 32 + row][ch * 4], vp + (size_t)row * L + jn + ch * 4);
            }
            if (tid < 16) cp16(&lzsh[ob * 64 + tid * 4], lzp + jn + tid * 4);
            CP_COMMIT();
        }

        // ---- E = Q^T K (64j x 128k) ----
        float e[2][4][4];
#pragma unroll
        for (int mt = 0; mt < 2; mt++)
#pragma unroll
            for (int nt = 0; nt < 4; nt++)
#pragma unroll
                for (int c = 0; c < 4; c++) e[mt][nt][c] = 0.f;

#pragma unroll
        for (int ksl = 0; ksl < 4; ksl++) {
            int kd = ksl * 8;
            unsigned a[2][4];
#pragma unroll
            for (int mt = 0; mt < 2; mt++) {
                int r = buf * 64 + m0q + mt * 16 + g;
                a[mt][0] = __float_as_uint(qsT[r    ][kd + t    ]);
                a[mt][1] = __float_as_uint(qsT[r + 8][kd + t    ]);
                a[mt][2] = __float_as_uint(qsT[r    ][kd + t + 4]);
                a[mt][3] = __float_as_uint(qsT[r + 8][kd + t + 4]);
            }
#pragma unroll
            for (int nt = 0; nt < 4; nt++) {
                unsigned b0 = __float_as_uint(ks2[kd + t    ][nbq + nt * 8 + g]);
                unsigned b1 = __float_as_uint(ks2[kd + t + 4][nbq + nt * 8 + g]);
                mma_tf32(e[0][nt], a[0][0], a[0][1], a[0][2], a[0][3], b0, b1);
                mma_tf32(e[1][nt], a[1][0], a[1][1], a[1][2], a[1][3], b0, b1);
            }
        }

        // ---- P = exp2(E + lz_j) -> ps ----
#pragma unroll
        for (int mt = 0; mt < 2; mt++) {
            int r = m0q + mt * 16 + g;
            float lz0 = lzsh[buf * 64 + r], lz1 = lzsh[buf * 64 + r + 8];
#pragma unroll
            for (int nt = 0; nt < 4; nt++) {
                int col = nbq + nt * 8 + 2 * t;
                *(float2*)&ps[r    ][col] = make_float2(ex2(e[mt][nt][0] + lz0),
                                                        ex2(e[mt][nt][1] + lz0));
                *(float2*)&ps[r + 8][col] = make_float2(ex2(e[mt][nt][2] + lz1),
                                                        ex2(e[mt][nt][3] + lz1));
            }
        }
        __syncthreads();

        // ---- acc += V * P  (M=32 d, N=128 k, K=64 j split across kh) ----
#pragma unroll
        for (int ksl = 0; ksl < 4; ksl++) {
            int kd = kjb + ksl * 8;
            unsigned a0 = __float_as_uint(ws[buf * 32 + m0p + g    ][kd + t    ]);
            unsigned a1 = __float_as_uint(ws[buf * 32 + m0p + g + 8][kd + t    ]);
            unsigned a2 = __float_as_uint(ws[buf * 32 + m0p + g    ][kd + t + 4]);
            unsigned a3 = __float_as_uint(ws[buf * 32 + m0p + g + 8][kd + t + 4]);
#pragma unroll
            for (int nt = 0; nt < 8; nt++) {
                unsigned b0 = __float_as_uint(ps[kd + t    ][nbp + nt * 8 + g]);
                unsigned b1 = __float_as_uint(ps[kd + t + 4][nbp + nt * 8 + g]);
                mma_tf32(acc[nt], a0, a1, a2, a3, b0, b1);
            }
        }
        buf ^= 1;
    }

    // ---- split-K reduction across kh pairs (reuse ps), then epilogue ----
    __syncthreads();
    if (kh == 1) {
#pragma unroll
        for (int nt = 0; nt < 8; nt++) {
            int col = nbp + nt * 8 + 2 * t;
            *(float2*)&ps[m0p + g    ][col] = make_float2(acc[nt][0], acc[nt][1]);
            *(float2*)&ps[m0p + g + 8][col] = make_float2(acc[nt][2], acc[nt][3]);
        }
    }
    __syncthreads();
    if (kh == 0) {
        int b = bg >> 3, gh = bg & 7;
#pragma unroll
        for (int nt = 0; nt < 8; nt++) {
            int col = nbp + nt * 8 + 2 * t;
            float2 r0 = *(float2*)&ps[m0p + g    ][col];
            float2 r1 = *(float2*)&ps[m0p + g + 8][col];
            int gcol = k0 + col;
            if (gcol < L) {
                size_t b0 = ((size_t)b * CH + gh * HD + m0p + g) * L + gcol;
                size_t b1 = b0 + (size_t)8 * L;
                out[b0    ] = acc[nt][0] + r0.x + x[b0    ];
                out[b0 + 1] = acc[nt][1] + r0.y + x[b0 + 1];
                out[b1    ] = acc[nt][2] + r1.x + x[b1    ];
                out[b1 + 1] = acc[nt][3] + r1.y + x[b1 + 1];
            }
        }
    }
}

// ---------------------------------------------------------------------------
extern "C" void kernel_launch(void* const* d_in, const int* in_sizes, int n_in,
                              void* d_out, int out_size)
{
    (void)in_sizes; (void)n_in; (void)out_size;
    const float* x  = (const float*)d_in[0];
    const float* Wq = (const float*)d_in[1];
    const float* bq = (const float*)d_in[2];
    const float* Wk = (const float*)d_in[3];
    const float* bk = (const float*)d_in[4];
    const float* Wv = (const float*)d_in[5];
    const float* bv = (const float*)d_in[6];
    float* out = (float*)d_out;

    const int SMEM2 = (32 * 136 + 2 * 64 * 36 + 2 * 32 * 68 + 64 * 136 + 2 * 64) * 4;
    cudaFuncSetAttribute(pass2_kernel, cudaFuncAttributeMaxDynamicSharedMemorySize, SMEM2);

    qkv_kernel<<<dim3(NT, BG), 256>>>(x, Wq, bq, Wk, bk, Wv, bv);
    pass1_kernel<<<dim3(NT, BG), 256>>>();
    pass2_kernel<<<dim3(NKT, BG), 256, SMEM2>>>(x, out);
}

// round 11
// speedup vs baseline: 9.6733x; 1.5078x over previous
#include <cuda_runtime.h>
#include <cuda_fp16.h>

// Problem constants
#define BATCH 4
#define CH    256
#define G     8
#define HD    32
#define L     3136      // 56*56
#define BG    32        // BATCH*G
#define NT    49        // 64-wide j tiles
#define NKT   25        // 128-wide k tiles (last covers only 64 cols)
#define LOG2E 1.4426950408889634f

// Scratch (static device arrays). fp16 operands, fp32 stats.
__device__ __align__(256) __half g_qh[(size_t)BG * L * HD];  // (bg, l, d) q*log2e
__device__ __align__(256) __half g_kh[(size_t)BG * L * HD];  // (bg, k, d) transposed
__device__ __align__(256) __half g_vh[(size_t)BG * HD * L];  // (bg, d, l)
__device__ __align__(256) float  g_lz[BG * L];               // -log2(row sum)

struct alignas(16) H8 { __half2 h[4]; };

// ---------------------------------------------------------------------------
// helpers
// ---------------------------------------------------------------------------
__device__ __forceinline__ float ex2(float x) {
    float r;
    asm("ex2.approx.ftz.f32 %0, %1;" : "=f"(r) : "f"(x));
    return r;
}

__device__ __forceinline__ void cp16(void* smem_dst, const void* gsrc) {
    unsigned s = (unsigned)__cvta_generic_to_shared(smem_dst);
    asm volatile("cp.async.cg.shared.global [%0], [%1], 16;" :: "r"(s), "l"(gsrc));
}
#define CP_COMMIT() asm volatile("cp.async.commit_group;")
#define CP_WAIT0()  asm volatile("cp.async.wait_group 0;")

// fp16 mma m16n8k16, fp32 accum.
// A row-major frag: a0={A[g][2t],A[g][2t+1]} a1={A[g+8][2t],..} a2={A[g][2t+8],..} a3={A[g+8][2t+8],..}
// B frag: b0={B[2t][g],B[2t+1][g]} b1={B[2t+8][g],B[2t+9][g]}   (first idx = K, second = N)
// C: c0=(g,2t) c1=(g,2t+1) c2=(g+8,2t) c3=(g+8,2t+1)
__device__ __forceinline__ void mma_f16(float c[4],
                                        unsigned a0, unsigned a1, unsigned a2, unsigned a3,
                                        unsigned b0, unsigned b1)
{
    asm volatile(
        "mma.sync.aligned.m16n8k16.row.col.f32.f16.f16.f32 "
        "{%0,%1,%2,%3}, {%4,%5,%6,%7}, {%8,%9}, {%0,%1,%2,%3};"
        : "+f"(c[0]), "+f"(c[1]), "+f"(c[2]), "+f"(c[3])
        : "r"(a0), "r"(a1), "r"(a2), "r"(a3), "r"(b0), "r"(b1));
}

__device__ __forceinline__ unsigned ldh2(const __half* p) {
    return *(const unsigned*)p;   // 4B-aligned half2 load
}

// ---------------------------------------------------------------------------
// Kernel 1: grouped 1x1 conv -> q (scaled, fp16, [l][d]), k (fp16, [k][d]), v ([d][l]).
// grid (49, 32), block 256
// ---------------------------------------------------------------------------
__global__ void __launch_bounds__(256, 3)
qkv_kernel(const float* __restrict__ x,
           const float* __restrict__ Wq, const float* __restrict__ bq,
           const float* __restrict__ Wk, const float* __restrict__ bk,
           const float* __restrict__ Wv, const float* __restrict__ bv)
{
    int bg = blockIdx.y;
    int l0 = blockIdx.x * 64;
    int b = bg >> 3, g = bg & 7;

    __shared__ float wqs[HD * HD], wks[HD * HD], wvs[HD * HD];
    __shared__ float bqs[HD], bks[HD], bvs[HD];
    __shared__ float xs[HD][64];

    int tid = threadIdx.x;
    for (int i = tid; i < HD * HD; i += 256) {
        wqs[i] = Wq[g * HD * HD + i] * LOG2E;
        wks[i] = Wk[g * HD * HD + i];
        wvs[i] = Wv[g * HD * HD + i];
    }
    if (tid < HD) {
        bqs[tid] = bq[g * HD + tid] * LOG2E;
        bks[tid] = bk[g * HD + tid];
        bvs[tid] = bv[g * HD + tid];
    }
    const float* xp = x + ((size_t)b * CH + g * HD) * L + l0;
    for (int i = tid; i < HD * 64; i += 256) {
        int d = i >> 6, l = i & 63;
        xs[d][l] = xp[(size_t)d * L + l];
    }
    __syncthreads();

    int l  = tid & 63;
    int o0 = (tid >> 6) * 8;
    float qa[8], ka[8], va[8];
#pragma unroll
    for (int r = 0; r < 8; r++) { qa[r] = bqs[o0 + r]; ka[r] = bks[o0 + r]; va[r] = bvs[o0 + r]; }
#pragma unroll
    for (int i = 0; i < HD; i++) {
        float xv = xs[i][l];
#pragma unroll
        for (int r = 0; r < 8; r++) {
            qa[r] += wqs[(o0 + r) * HD + i] * xv;
            ka[r] += wks[(o0 + r) * HD + i] * xv;
            va[r] += wvs[(o0 + r) * HD + i] * xv;
        }
    }
    size_t base = ((size_t)bg * L + l0 + l) * HD + o0;
    H8 qp8, kp8;
#pragma unroll
    for (int r = 0; r < 8; r += 2) {
        qp8.h[r >> 1] = __floats2half2_rn(qa[r], qa[r + 1]);
        kp8.h[r >> 1] = __floats2half2_rn(ka[r], ka[r + 1]);
    }
    *(H8*)&g_qh[base] = qp8;
    *(H8*)&g_kh[base] = kp8;
    size_t vbase = ((size_t)bg * HD + o0) * L + l0 + l;
#pragma unroll
    for (int r = 0; r < 8; r++)
        g_vh[vbase + (size_t)r * L] = __float2half_rn(va[r]);
}

// ---------------------------------------------------------------------------
// Kernel 2: Z_j = sum_k exp2(e[j,k]); stores -log2(Z).
// grid (49 j-tiles, 32 bg), block 256. Block tile 64j x 128k.
// Warp (wj=w>>2, wk=w&3) -> 32j x 32k. fp16 m16n8k16, cp.async double buffer.
// ---------------------------------------------------------------------------
__global__ void __launch_bounds__(256) pass1_kernel()
{
    int bg = blockIdx.y;
    int j0 = blockIdx.x * 64;

    __shared__ __half qs[64][40];        // [j][d]
    __shared__ __half ks[2][128][40];    // [buf][kcol][d]
    __shared__ float zsh[64];

    int tid = threadIdx.x;
    int w = tid >> 5, lane = tid & 31;
    int g = lane >> 2, t = lane & 3;
    int wj = w >> 2, wk = w & 3;
    int m0 = wj * 32, nb = wk * 32;

    const __half* qp = g_qh + (size_t)bg * L * HD;
    const __half* kp = g_kh + (size_t)bg * L * HD;

    // first K tile (kt=0) into buf 0: 128 rows x 4 chunks of 16B
#pragma unroll
    for (int r = 0; r < 2; r++) {
        int task = tid + 256 * r;
        int row = task >> 2, ch = task & 3;
        cp16(&ks[0][row][ch * 8], kp + (size_t)row * HD + ch * 8);
    }
    CP_COMMIT();

    // Q tile: 64 rows x 4 chunks
    {
        int row = tid >> 2, ch = tid & 3;
        *(uint4*)&qs[row][ch * 8] = *(const uint4*)(qp + (size_t)(j0 + row) * HD + ch * 8);
    }
    if (tid < 64) zsh[tid] = 0.f;

    float s[2][2] = {{0.f, 0.f}, {0.f, 0.f}};
    int buf = 0;

    for (int kt = 0; kt < NKT; kt++) {
        CP_WAIT0();
        __syncthreads();

        if (kt + 1 < NKT) {
            int kbase = (kt + 1) * 128;
#pragma unroll
            for (int r = 0; r < 2; r++) {
                int task = tid + 256 * r;
                int row = task >> 2, ch = task & 3;
                int col = kbase + row;
                if (col < L)
                    cp16(&ks[buf ^ 1][row][ch * 8], kp + (size_t)col * HD + ch * 8);
            }
            CP_COMMIT();
        }

        float e[2][4][4];
#pragma unroll
        for (int mt = 0; mt < 2; mt++)
#pragma unroll
            for (int nt = 0; nt < 4; nt++)
#pragma unroll
                for (int c = 0; c < 4; c++) e[mt][nt][c] = 0.f;

#pragma unroll
        for (int s16 = 0; s16 < 2; s16++) {
            int kd = s16 * 16;
            unsigned a[2][4];
#pragma unroll
            for (int mt = 0; mt < 2; mt++) {
                int r = m0 + mt * 16 + g;
                a[mt][0] = ldh2(&qs[r    ][kd + 2 * t    ]);
                a[mt][1] = ldh2(&qs[r + 8][kd + 2 * t    ]);
                a[mt][2] = ldh2(&qs[r    ][kd + 2 * t + 8]);
                a[mt][3] = ldh2(&qs[r + 8][kd + 2 * t + 8]);
            }
#pragma unroll
            for (int nt = 0; nt < 4; nt++) {
                int n = nb + nt * 8 + g;
                unsigned b0 = ldh2(&ks[buf][n][kd + 2 * t    ]);
                unsigned b1 = ldh2(&ks[buf][n][kd + 2 * t + 8]);
                mma_f16(e[0][nt], a[0][0], a[0][1], a[0][2], a[0][3], b0, b1);
                mma_f16(e[1][nt], a[1][0], a[1][1], a[1][2], a[1][3], b0, b1);
            }
        }

        // tail tile: warps wk>=2 fully past L -> skip (stale smem harmless)
        if (kt < NKT - 1 || wk < 2) {
#pragma unroll
            for (int mt = 0; mt < 2; mt++)
#pragma unroll
                for (int nt = 0; nt < 4; nt++) {
                    s[mt][0] += ex2(e[mt][nt][0]) + ex2(e[mt][nt][1]);
                    s[mt][1] += ex2(e[mt][nt][2]) + ex2(e[mt][nt][3]);
                }
        }
        buf ^= 1;
    }

#pragma unroll
    for (int mask = 1; mask <= 2; mask <<= 1)
#pragma unroll
        for (int mt = 0; mt < 2; mt++)
#pragma unroll
            for (int r = 0; r < 2; r++)
                s[mt][r] += __shfl_xor_sync(0xffffffffu, s[mt][r], mask);
    if (t == 0) {
        atomicAdd(&zsh[m0 + g     ], s[0][0]);
        atomicAdd(&zsh[m0 + g + 8 ], s[0][1]);
        atomicAdd(&zsh[m0 + g + 16], s[1][0]);
        atomicAdd(&zsh[m0 + g + 24], s[1][1]);
    }
    __syncthreads();
    if (tid < 64) g_lz[bg * L + j0 + tid] = -log2f(zsh[tid]);
}

// ---------------------------------------------------------------------------
// Kernel 3: out[d,k] = sum_j exp2(e[j,k] + lz_j) * v[d,j]  (+ x residual)
// grid (25 k-tiles, 32 bg), block 256, dynamic smem (~48.6 KB).
// QK: warp (wj=w>>2, wk=w&3) -> 32j x 32k of 64x128 E tile. P stored transposed [k][j] fp16.
// PV: kh=w>>2 (j-half), wm=(w>>1)&1 (16 d rows), wn=w&1 (64 k cols).
// ---------------------------------------------------------------------------
__global__ void __launch_bounds__(256) pass2_kernel(const float* __restrict__ x,
                                                    float* __restrict__ out)
{
    extern __shared__ __half smh[];
    __half (*ks2)[40] = (__half(*)[40])smh;                  // 128k x 40  (5120)
    __half (*qs)[40]  = (__half(*)[40])(smh + 5120);         // 2 x 64j x 40 (5120)
    __half (*ws)[72]  = (__half(*)[72])(smh + 10240);        // 2 x 32d x 72 (4608)
    __half (*psT)[72] = (__half(*)[72])(smh + 14848);        // 128k x 72j (9216)
    float* lzsh       = (float*)(smh + 24064);               // 2 x 64
    float* red        = (float*)psT;                          // epilogue scratch [32][130]

    int bg = blockIdx.y;
    int k0 = blockIdx.x * 128;
    int tid = threadIdx.x;
    int w = tid >> 5, lane = tid & 31;
    int g = lane >> 2, t = lane & 3;
    int wj = w >> 2, wk = w & 3;
    int m0q = wj * 32, nbq = wk * 32;
    int kh = w >> 2, wm = (w >> 1) & 1, wn = w & 1;
    int m0p = wm * 16, nbp = wn * 64;

    const __half* qp  = g_qh + (size_t)bg * L * HD;
    const __half* kp  = g_kh + (size_t)bg * L * HD;
    const __half* vp  = g_vh + (size_t)bg * HD * L;
    const float*  lzp = g_lz + bg * L;

    // first j-tile (jt=0) into buf 0
    {
        int row = tid >> 2, ch = tid & 3;                    // qs: 64 x 4 chunks
        cp16(&qs[row][ch * 8], qp + (size_t)row * HD + ch * 8);
        int vrow = tid >> 3, vch = tid & 7;                  // ws: 32 x 8 chunks
        cp16(&ws[vrow][vch * 8], vp + (size_t)vrow * L + vch * 8);
        if (tid < 16) cp16(&lzsh[tid * 4], lzp + tid * 4);
        CP_COMMIT();
    }

    // K tile for our 128 columns, zero-filled past L (once)
#pragma unroll
    for (int r = 0; r < 2; r++) {
        int task = tid + 256 * r;
        int row = task >> 2, ch = task & 3;
        int col = k0 + row;
        if (col < L)
            *(uint4*)&ks2[row][ch * 8] = *(const uint4*)(kp + (size_t)col * HD + ch * 8);
        else
            *(uint4*)&ks2[row][ch * 8] = make_uint4(0, 0, 0, 0);
    }

    float acc[8][4];
#pragma unroll
    for (int nt = 0; nt < 8; nt++)
#pragma unroll
        for (int c = 0; c < 4; c++) acc[nt][c] = 0.f;

    int buf = 0;
    for (int jt = 0; jt < NT; jt++) {
        CP_WAIT0();
        __syncthreads();   // buf tiles ready; prev PV done with psT

        if (jt + 1 < NT) {
            int jn = (jt + 1) * 64;
            int ob = buf ^ 1;
            int row = tid >> 2, ch = tid & 3;
            cp16(&qs[ob * 64 + row][ch * 8], qp + (size_t)(jn + row) * HD + ch * 8);
            int vrow = tid >> 3, vch = tid & 7;
            cp16(&ws[ob * 32 + vrow][vch * 8], vp + (size_t)vrow * L + jn + vch * 8);
            if (tid < 16) cp16(&lzsh[ob * 64 + tid * 4], lzp + jn + tid * 4);
            CP_COMMIT();
        }

        // ---- E = Q^T K (64j x 128k) ----
        float e[2][4][4];
#pragma unroll
        for (int mt = 0; mt < 2; mt++)
#pragma unroll
            for (int nt = 0; nt < 4; nt++)
#pragma unroll
                for (int c = 0; c < 4; c++) e[mt][nt][c] = 0.f;

#pragma unroll
        for (int s16 = 0; s16 < 2; s16++) {
            int kd = s16 * 16;
            unsigned a[2][4];
#pragma unroll
            for (int mt = 0; mt < 2; mt++) {
                int r = buf * 64 + m0q + mt * 16 + g;
                a[mt][0] = ldh2(&qs[r    ][kd + 2 * t    ]);
                a[mt][1] = ldh2(&qs[r + 8][kd + 2 * t    ]);
                a[mt][2] = ldh2(&qs[r    ][kd + 2 * t + 8]);
                a[mt][3] = ldh2(&qs[r + 8][kd + 2 * t + 8]);
            }
#pragma unroll
            for (int nt = 0; nt < 4; nt++) {
                int n = nbq + nt * 8 + g;
                unsigned b0 = ldh2(&ks2[n][kd + 2 * t    ]);
                unsigned b1 = ldh2(&ks2[n][kd + 2 * t + 8]);
                mma_f16(e[0][nt], a[0][0], a[0][1], a[0][2], a[0][3], b0, b1);
                mma_f16(e[1][nt], a[1][0], a[1][1], a[1][2], a[1][3], b0, b1);
            }
        }

        // ---- P = exp2(E + lz_j) -> psT[k][j] fp16 ----
#pragma unroll
        for (int mt = 0; mt < 2; mt++) {
            int r = m0q + mt * 16 + g;
            float lz0 = lzsh[buf * 64 + r], lz1 = lzsh[buf * 64 + r + 8];
#pragma unroll
            for (int nt = 0; nt < 4; nt++) {
                int col = nbq + nt * 8 + 2 * t;
                psT[col    ][r    ] = __float2half_rn(ex2(e[mt][nt][0] + lz0));
                psT[col + 1][r    ] = __float2half_rn(ex2(e[mt][nt][1] + lz0));
                psT[col    ][r + 8] = __float2half_rn(ex2(e[mt][nt][2] + lz1));
                psT[col + 1][r + 8] = __float2half_rn(ex2(e[mt][nt][3] + lz1));
            }
        }
        __syncthreads();

        // ---- acc += V * P  (M=32 d, N=128 k, K=64 j; j split across kh) ----
#pragma unroll
        for (int s16 = 0; s16 < 2; s16++) {
            int kd = kh * 32 + s16 * 16;
            unsigned a0 = ldh2(&ws[buf * 32 + m0p + g    ][kd + 2 * t    ]);
            unsigned a1 = ldh2(&ws[buf * 32 + m0p + g + 8][kd + 2 * t    ]);
            unsigned a2 = ldh2(&ws[buf * 32 + m0p + g    ][kd + 2 * t + 8]);
            unsigned a3 = ldh2(&ws[buf * 32 + m0p + g + 8][kd + 2 * t + 8]);
#pragma unroll
            for (int nt = 0; nt < 8; nt++) {
                int n = nbp + nt * 8 + g;
                unsigned b0 = ldh2(&psT[n][kd + 2 * t    ]);
                unsigned b1 = ldh2(&psT[n][kd + 2 * t + 8]);
                mma_f16(acc[nt], a0, a1, a2, a3, b0, b1);
            }
        }
        buf ^= 1;
    }

    // ---- split-K reduction across kh pairs (reuse psT as fp32 scratch) ----
    __syncthreads();
    if (kh == 1) {
#pragma unroll
        for (int nt = 0; nt < 8; nt++) {
            int col = nbp + nt * 8 + 2 * t;
            *(float2*)&red[(m0p + g    ) * 130 + col] = make_float2(acc[nt][0], acc[nt][1]);
            *(float2*)&red[(m0p + g + 8) * 130 + col] = make_float2(acc[nt][2], acc[nt][3]);
        }
    }
    __syncthreads();
    if (kh == 0) {
        int b = bg >> 3, gh = bg & 7;
#pragma unroll
        for (int nt = 0; nt < 8; nt++) {
            int col = nbp + nt * 8 + 2 * t;
            float2 r0 = *(float2*)&red[(m0p + g    ) * 130 + col];
            float2 r1 = *(float2*)&red[(m0p + g + 8) * 130 + col];
            int gcol = k0 + col;
            if (gcol < L) {
                size_t b0 = ((size_t)b * CH + gh * HD + m0p + g) * L + gcol;
                size_t b1 = b0 + (size_t)8 * L;
                out[b0    ] = acc[nt][0] + r0.x + x[b0    ];
                out[b0 + 1] = acc[nt][1] + r0.y + x[b0 + 1];
                out[b1    ] = acc[nt][2] + r1.x + x[b1    ];
                out[b1 + 1] = acc[nt][3] + r1.y + x[b1 + 1];
            }
        }
    }
}

// ---------------------------------------------------------------------------
extern "C" void kernel_launch(void* const* d_in, const int* in_sizes, int n_in,
                              void* d_out, int out_size)
{
    (void)in_sizes; (void)n_in; (void)out_size;
    const float* x  = (const float*)d_in[0];
    const float* Wq = (const float*)d_in[1];
    const float* bq = (const float*)d_in[2];
    const float* Wk = (const float*)d_in[3];
    const float* bk = (const float*)d_in[4];
    const float* Wv = (const float*)d_in[5];
    const float* bv = (const float*)d_in[6];
    float* out = (float*)d_out;

    const int SMEM2 = 24320 * 2 + 256;   // halfs*2 bytes + lz floats slack
    cudaFuncSetAttribute(pass2_kernel, cudaFuncAttributeMaxDynamicSharedMemorySize, SMEM2);

    qkv_kernel<<<dim3(NT, BG), 256>>>(x, Wq, bq, Wk, bk, Wv, bv);
    pass1_kernel<<<dim3(NT, BG), 256>>>();
    pass2_kernel<<<dim3(NKT, BG), 256, SMEM2>>>(x, out);
}

// round 13
// speedup vs baseline: 9.9153x; 1.0250x over previous
#include <cuda_runtime.h>
#include <cuda_fp16.h>

// Problem constants
#define BATCH 4
#define CH    256
#define G     8
#define HD    32
#define L     3136      // 56*56
#define BG    32        // BATCH*G
#define NT    49        // 64-wide j tiles
#define NKT   25        // 128-wide k tiles (last covers only 64 cols)
#define LOG2E 1.4426950408889634f

// Scratch (static device arrays). fp16 operands, fp32 stats.
__device__ __align__(256) __half g_qh[(size_t)BG * L * HD];  // (bg, l, d) q*log2e
__device__ __align__(256) __half g_kh[(size_t)BG * L * HD];  // (bg, k, d) transposed
__device__ __align__(256) __half g_vh[(size_t)BG * HD * L];  // (bg, d, l)
__device__ __align__(256) float  g_lz[BG * L];               // -log2(row sum)

struct alignas(16) H8 { __half2 h[4]; };

// ---------------------------------------------------------------------------
// helpers
// ---------------------------------------------------------------------------
__device__ __forceinline__ float ex2(float x) {
    float r;
    asm("ex2.approx.ftz.f32 %0, %1;" : "=f"(r) : "f"(x));
    return r;
}

__device__ __forceinline__ void cp16(void* smem_dst, const void* gsrc) {
    unsigned s = (unsigned)__cvta_generic_to_shared(smem_dst);
    asm volatile("cp.async.cg.shared.global [%0], [%1], 16;" :: "r"(s), "l"(gsrc));
}
#define CP_COMMIT() asm volatile("cp.async.commit_group;")
#define CP_WAIT0()  asm volatile("cp.async.wait_group 0;")

// fp16 mma m16n8k16, fp32 accum.
__device__ __forceinline__ void mma_f16(float c[4],
                                        unsigned a0, unsigned a1, unsigned a2, unsigned a3,
                                        unsigned b0, unsigned b1)
{
    asm volatile(
        "mma.sync.aligned.m16n8k16.row.col.f32.f16.f16.f32 "
        "{%0,%1,%2,%3}, {%4,%5,%6,%7}, {%8,%9}, {%0,%1,%2,%3};"
        : "+f"(c[0]), "+f"(c[1]), "+f"(c[2]), "+f"(c[3])
        : "r"(a0), "r"(a1), "r"(a2), "r"(a3), "r"(b0), "r"(b1));
}

__device__ __forceinline__ unsigned ldh2(const __half* p) {
    return *(const unsigned*)p;   // 4B-aligned half2 load
}

// ---------------------------------------------------------------------------
// Kernel 1: grouped 1x1 conv -> q (scaled, fp16, [l][d]), k (fp16, [k][d]), v ([d][l]).
// grid (49, 32), block 256. x staged transposed [l][d]; float4 smem reads.
// ---------------------------------------------------------------------------
__global__ void __launch_bounds__(256, 3)
qkv_kernel(const float* __restrict__ x,
           const float* __restrict__ Wq, const float* __restrict__ bq,
           const float* __restrict__ Wk, const float* __restrict__ bk,
           const float* __restrict__ Wv, const float* __restrict__ bv)
{
    int bg = blockIdx.y;
    int l0 = blockIdx.x * 64;
    int b = bg >> 3, g = bg & 7;

    __shared__ float wqs[HD * HD], wks[HD * HD], wvs[HD * HD];
    __shared__ float bqs[HD], bks[HD], bvs[HD];
    __shared__ float xst[64][36];   // [l][d], pad 36

    int tid = threadIdx.x;
    for (int i = tid; i < HD * HD; i += 256) {
        wqs[i] = Wq[g * HD * HD + i] * LOG2E;
        wks[i] = Wk[g * HD * HD + i];
        wvs[i] = Wv[g * HD * HD + i];
    }
    if (tid < HD) {
        bqs[tid] = bq[g * HD + tid] * LOG2E;
        bks[tid] = bk[g * HD + tid];
        bvs[tid] = bv[g * HD + tid];
    }
    const float* xp = x + ((size_t)b * CH + g * HD) * L + l0;
    for (int i = tid; i < HD * 64; i += 256) {
        int d = i >> 6, l = i & 63;
        xst[l][d] = xp[(size_t)d * L + l];   // coalesced gmem read over l
    }
    __syncthreads();

    int l  = tid & 63;
    int o0 = (tid >> 6) * 8;
    float qa[8], ka[8], va[8];
#pragma unroll
    for (int r = 0; r < 8; r++) { qa[r] = bqs[o0 + r]; ka[r] = bks[o0 + r]; va[r] = bvs[o0 + r]; }

#pragma unroll
    for (int i4 = 0; i4 < 8; i4++) {
        float4 xv = *(const float4*)&xst[l][i4 * 4];
#pragma unroll
        for (int r = 0; r < 8; r++) {
            int wo = (o0 + r) * HD + i4 * 4;
            float4 wq = *(const float4*)&wqs[wo];
            float4 wk = *(const float4*)&wks[wo];
            float4 wv = *(const float4*)&wvs[wo];
            qa[r] += wq.x * xv.x + wq.y * xv.y + wq.z * xv.z + wq.w * xv.w;
            ka[r] += wk.x * xv.x + wk.y * xv.y + wk.z * xv.z + wk.w * xv.w;
            va[r] += wv.x * xv.x + wv.y * xv.y + wv.z * xv.z + wv.w * xv.w;
        }
    }

    size_t base = ((size_t)bg * L + l0 + l) * HD + o0;
    H8 qp8, kp8;
#pragma unroll
    for (int r = 0; r < 8; r += 2) {
        qp8.h[r >> 1] = __floats2half2_rn(qa[r], qa[r + 1]);
        kp8.h[r >> 1] = __floats2half2_rn(ka[r], ka[r + 1]);
    }
    *(H8*)&g_qh[base] = qp8;
    *(H8*)&g_kh[base] = kp8;
    size_t vbase = ((size_t)bg * HD + o0) * L + l0 + l;
#pragma unroll
    for (int r = 0; r < 8; r++)
        g_vh[vbase + (size_t)r * L] = __float2half_rn(va[r]);
}

// ---------------------------------------------------------------------------
// Kernel 2: Z_j = sum_k exp2(e[j,k]); stores -log2(Z).
// grid (49 j-tiles, 32 bg), block 256. Block tile 64j x 128k. fp32 MUFU.
// ---------------------------------------------------------------------------
__global__ void __launch_bounds__(256) pass1_kernel()
{
    int bg = blockIdx.y;
    int j0 = blockIdx.x * 64;

    __shared__ __half qs[64][40];        // [j][d]
    __shared__ __half ks[2][128][40];    // [buf][kcol][d]
    __shared__ float zsh[64];

    int tid = threadIdx.x;
    int w = tid >> 5, lane = tid & 31;
    int g = lane >> 2, t = lane & 3;
    int wj = w >> 2, wk = w & 3;
    int m0 = wj * 32, nb = wk * 32;

    const __half* qp = g_qh + (size_t)bg * L * HD;
    const __half* kp = g_kh + (size_t)bg * L * HD;

#pragma unroll
    for (int r = 0; r < 2; r++) {
        int task = tid + 256 * r;
        int row = task >> 2, ch = task & 3;
        cp16(&ks[0][row][ch * 8], kp + (size_t)row * HD + ch * 8);
    }
    CP_COMMIT();

    {
        int row = tid >> 2, ch = tid & 3;
        *(uint4*)&qs[row][ch * 8] = *(const uint4*)(qp + (size_t)(j0 + row) * HD + ch * 8);
    }
    if (tid < 64) zsh[tid] = 0.f;

    float s[2][2] = {{0.f, 0.f}, {0.f, 0.f}};
    int buf = 0;

    for (int kt = 0; kt < NKT; kt++) {
        CP_WAIT0();
        __syncthreads();

        if (kt + 1 < NKT) {
            int kbase = (kt + 1) * 128;
#pragma unroll
            for (int r = 0; r < 2; r++) {
                int task = tid + 256 * r;
                int row = task >> 2, ch = task & 3;
                int col = kbase + row;
                if (col < L)
                    cp16(&ks[buf ^ 1][row][ch * 8], kp + (size_t)col * HD + ch * 8);
            }
            CP_COMMIT();
        }

        float e[2][4][4];
#pragma unroll
        for (int mt = 0; mt < 2; mt++)
#pragma unroll
            for (int nt = 0; nt < 4; nt++)
#pragma unroll
                for (int c = 0; c < 4; c++) e[mt][nt][c] = 0.f;

#pragma unroll
        for (int s16 = 0; s16 < 2; s16++) {
            int kd = s16 * 16;
            unsigned a[2][4];
#pragma unroll
            for (int mt = 0; mt < 2; mt++) {
                int r = m0 + mt * 16 + g;
                a[mt][0] = ldh2(&qs[r    ][kd + 2 * t    ]);
                a[mt][1] = ldh2(&qs[r + 8][kd + 2 * t    ]);
                a[mt][2] = ldh2(&qs[r    ][kd + 2 * t + 8]);
                a[mt][3] = ldh2(&qs[r + 8][kd + 2 * t + 8]);
            }
#pragma unroll
            for (int nt = 0; nt < 4; nt++) {
                int n = nb + nt * 8 + g;
                unsigned b0 = ldh2(&ks[buf][n][kd + 2 * t    ]);
                unsigned b1 = ldh2(&ks[buf][n][kd + 2 * t + 8]);
                mma_f16(e[0][nt], a[0][0], a[0][1], a[0][2], a[0][3], b0, b1);
                mma_f16(e[1][nt], a[1][0], a[1][1], a[1][2], a[1][3], b0, b1);
            }
        }

        if (kt < NKT - 1 || wk < 2) {
#pragma unroll
            for (int mt = 0; mt < 2; mt++)
#pragma unroll
                for (int nt = 0; nt < 4; nt++) {
                    s[mt][0] += ex2(e[mt][nt][0]) + ex2(e[mt][nt][1]);
                    s[mt][1] += ex2(e[mt][nt][2]) + ex2(e[mt][nt][3]);
                }
        }
        buf ^= 1;
    }

#pragma unroll
    for (int mask = 1; mask <= 2; mask <<= 1)
#pragma unroll
        for (int mt = 0; mt < 2; mt++)
#pragma unroll
            for (int r = 0; r < 2; r++)
                s[mt][r] += __shfl_xor_sync(0xffffffffu, s[mt][r], mask);
    if (t == 0) {
        atomicAdd(&zsh[m0 + g     ], s[0][0]);
        atomicAdd(&zsh[m0 + g + 8 ], s[0][1]);
        atomicAdd(&zsh[m0 + g + 16], s[1][0]);
        atomicAdd(&zsh[m0 + g + 24], s[1][1]);
    }
    __syncthreads();
    if (tid < 64) g_lz[bg * L + j0 + tid] = -log2f(zsh[tid]);
}

// ---------------------------------------------------------------------------
// Kernel 3: out[d,k] = sum_j exp2(e[j,k] + lz_j) * v[d,j]  (+ x residual)
// grid (25 k-tiles, 32 bg), block 256, dynamic smem (~48.6 KB). fp32 MUFU.
// ---------------------------------------------------------------------------
__global__ void __launch_bounds__(256) pass2_kernel(const float* __restrict__ x,
                                                    float* __restrict__ out)
{
    extern __shared__ __half smh[];
    __half (*ks2)[40] = (__half(*)[40])smh;                  // 128k x 40  (5120)
    __half (*qs)[40]  = (__half(*)[40])(smh + 5120);         // 2 x 64j x 40 (5120)
    __half (*ws)[72]  = (__half(*)[72])(smh + 10240);        // 2 x 32d x 72 (4608)
    __half (*psT)[72] = (__half(*)[72])(smh + 14848);        // 128k x 72j (9216)
    float* lzsh       = (float*)(smh + 24064);               // 2 x 64
    float* red        = (float*)psT;                          // epilogue scratch [32][130]

    int bg = blockIdx.y;
    int k0 = blockIdx.x * 128;
    int tid = threadIdx.x;
    int w = tid >> 5, lane = tid & 31;
    int g = lane >> 2, t = lane & 3;
    int wj = w >> 2, wk = w & 3;
    int m0q = wj * 32, nbq = wk * 32;
    int kh = w >> 2, wm = (w >> 1) & 1, wn = w & 1;
    int m0p = wm * 16, nbp = wn * 64;

    const __half* qp  = g_qh + (size_t)bg * L * HD;
    const __half* kp  = g_kh + (size_t)bg * L * HD;
    const __half* vp  = g_vh + (size_t)bg * HD * L;
    const float*  lzp = g_lz + bg * L;

    {
        int row = tid >> 2, ch = tid & 3;
        cp16(&qs[row][ch * 8], qp + (size_t)row * HD + ch * 8);
        int vrow = tid >> 3, vch = tid & 7;
        cp16(&ws[vrow][vch * 8], vp + (size_t)vrow * L + vch * 8);
        if (tid < 16) cp16(&lzsh[tid * 4], lzp + tid * 4);
        CP_COMMIT();
    }

#pragma unroll
    for (int r = 0; r < 2; r++) {
        int task = tid + 256 * r;
        int row = task >> 2, ch = task & 3;
        int col = k0 + row;
        if (col < L)
            *(uint4*)&ks2[row][ch * 8] = *(const uint4*)(kp + (size_t)col * HD + ch * 8);
        else
            *(uint4*)&ks2[row][ch * 8] = make_uint4(0, 0, 0, 0);
    }

    float acc[8][4];
#pragma unroll
    for (int nt = 0; nt < 8; nt++)
#pragma unroll
        for (int c = 0; c < 4; c++) acc[nt][c] = 0.f;

    int buf = 0;
    for (int jt = 0; jt < NT; jt++) {
        CP_WAIT0();
        __syncthreads();

        if (jt + 1 < NT) {
            int jn = (jt + 1) * 64;
            int ob = buf ^ 1;
            int row = tid >> 2, ch = tid & 3;
            cp16(&qs[ob * 64 + row][ch * 8], qp + (size_t)(jn + row) * HD + ch * 8);
            int vrow = tid >> 3, vch = tid & 7;
            cp16(&ws[ob * 32 + vrow][vch * 8], vp + (size_t)vrow * L + jn + vch * 8);
            if (tid < 16) cp16(&lzsh[ob * 64 + tid * 4], lzp + jn + tid * 4);
            CP_COMMIT();
        }

        // ---- E = Q^T K (64j x 128k) ----
        float e[2][4][4];
#pragma unroll
        for (int mt = 0; mt < 2; mt++)
#pragma unroll
            for (int nt = 0; nt < 4; nt++)
#pragma unroll
                for (int c = 0; c < 4; c++) e[mt][nt][c] = 0.f;

#pragma unroll
        for (int s16 = 0; s16 < 2; s16++) {
            int kd = s16 * 16;
            unsigned a[2][4];
#pragma unroll
            for (int mt = 0; mt < 2; mt++) {
                int r = buf * 64 + m0q + mt * 16 + g;
                a[mt][0] = ldh2(&qs[r    ][kd + 2 * t    ]);
                a[mt][1] = ldh2(&qs[r + 8][kd + 2 * t    ]);
                a[mt][2] = ldh2(&qs[r    ][kd + 2 * t + 8]);
                a[mt][3] = ldh2(&qs[r + 8][kd + 2 * t + 8]);
            }
#pragma unroll
            for (int nt = 0; nt < 4; nt++) {
                int n = nbq + nt * 8 + g;
                unsigned b0 = ldh2(&ks2[n][kd + 2 * t    ]);
                unsigned b1 = ldh2(&ks2[n][kd + 2 * t + 8]);
                mma_f16(e[0][nt], a[0][0], a[0][1], a[0][2], a[0][3], b0, b1);
                mma_f16(e[1][nt], a[1][0], a[1][1], a[1][2], a[1][3], b0, b1);
            }
        }

        // ---- P = exp2(E + lz_j) fp32 MUFU -> psT[k][j] fp16 ----
#pragma unroll
        for (int mt = 0; mt < 2; mt++) {
            int r = m0q + mt * 16 + g;
            float lz0 = lzsh[buf * 64 + r], lz1 = lzsh[buf * 64 + r + 8];
#pragma unroll
            for (int nt = 0; nt < 4; nt++) {
                int col = nbq + nt * 8 + 2 * t;
                psT[col    ][r    ] = __float2half_rn(ex2(e[mt][nt][0] + lz0));
                psT[col + 1][r    ] = __float2half_rn(ex2(e[mt][nt][1] + lz0));
                psT[col    ][r + 8] = __float2half_rn(ex2(e[mt][nt][2] + lz1));
                psT[col + 1][r + 8] = __float2half_rn(ex2(e[mt][nt][3] + lz1));
            }
        }
        __syncthreads();

        // ---- acc += V * P  (M=32 d, N=128 k, K=64 j; j split across kh) ----
#pragma unroll
        for (int s16 = 0; s16 < 2; s16++) {
            int kd = kh * 32 + s16 * 16;
            unsigned a0 = ldh2(&ws[buf * 32 + m0p + g    ][kd + 2 * t    ]);
            unsigned a1 = ldh2(&ws[buf * 32 + m0p + g + 8][kd + 2 * t    ]);
            unsigned a2 = ldh2(&ws[buf * 32 + m0p + g    ][kd + 2 * t + 8]);
            unsigned a3 = ldh2(&ws[buf * 32 + m0p + g + 8][kd + 2 * t + 8]);
#pragma unroll
            for (int nt = 0; nt < 8; nt++) {
                int n = nbp + nt * 8 + g;
                unsigned b0 = ldh2(&psT[n][kd + 2 * t    ]);
                unsigned b1 = ldh2(&psT[n][kd + 2 * t + 8]);
                mma_f16(acc[nt], a0, a1, a2, a3, b0, b1);
            }
        }
        buf ^= 1;
    }

    // ---- split-K reduction across kh pairs (reuse psT as fp32 scratch) ----
    __syncthreads();
    if (kh == 1) {
#pragma unroll
        for (int nt = 0; nt < 8; nt++) {
            int col = nbp + nt * 8 + 2 * t;
            *(float2*)&red[(m0p + g    ) * 130 + col] = make_float2(acc[nt][0], acc[nt][1]);
            *(float2*)&red[(m0p + g + 8) * 130 + col] = make_float2(acc[nt][2], acc[nt][3]);
        }
    }
    __syncthreads();
    if (kh == 0) {
        int b = bg >> 3, gh = bg & 7;
#pragma unroll
        for (int nt = 0; nt < 8; nt++) {
            int col = nbp + nt * 8 + 2 * t;
            float2 r0 = *(float2*)&red[(m0p + g    ) * 130 + col];
            float2 r1 = *(float2*)&red[(m0p + g + 8) * 130 + col];
            int gcol = k0 + col;
            if (gcol < L) {
                size_t b0 = ((size_t)b * CH + gh * HD + m0p + g) * L + gcol;
                size_t b1 = b0 + (size_t)8 * L;
                out[b0    ] = acc[nt][0] + r0.x + x[b0    ];
                out[b0 + 1] = acc[nt][1] + r0.y + x[b0 + 1];
                out[b1    ] = acc[nt][2] + r1.x + x[b1    ];
                out[b1 + 1] = acc[nt][3] + r1.y + x[b1 + 1];
            }
        }
    }
}

// ---------------------------------------------------------------------------
extern "C" void kernel_launch(void* const* d_in, const int* in_sizes, int n_in,
                              void* d_out, int out_size)
{
    (void)in_sizes; (void)n_in; (void)out_size;
    const float* x  = (const float*)d_in[0];
    const float* Wq = (const float*)d_in[1];
    const float* bq = (const float*)d_in[2];
    const float* Wk = (const float*)d_in[3];
    const float* bk = (const float*)d_in[4];
    const float* Wv = (const float*)d_in[5];
    const float* bv = (const float*)d_in[6];
    float* out = (float*)d_out;

    const int SMEM2 = 24320 * 2 + 256;
    cudaFuncSetAttribute(pass2_kernel, cudaFuncAttributeMaxDynamicSharedMemorySize, SMEM2);

    qkv_kernel<<<dim3(NT, BG), 256>>>(x, Wq, bq, Wk, bk, Wv, bv);
    pass1_kernel<<<dim3(NT, BG), 256>>>();
    pass2_kernel<<<dim3(NKT, BG), 256, SMEM2>>>(x, out);
}